// round 1
// baseline (speedup 1.0000x reference)
#include <cuda_runtime.h>
#include <math.h>

#define SEQ   4096
#define HID   2048
#define NH    16
#define NKV   8
#define HD    128

// ---------------- scratch (no allocation allowed) ----------------
__device__ float g_Q[SEQ * NH * HD];
__device__ float g_K[SEQ * NKV * HD];
__device__ float g_V[SEQ * NKV * HD];
__device__ float g_AO[SEQ * NH * HD];

// =================================================================
// Generic NT GEMM: C[M,N] = A[M,K] * B[N,K]^T   (all fp32, row-major)
// 128x128 tile, BK=16, 256 threads, 8x8 micro-tile.
// =================================================================
#define GBM 128
#define GBN 128
#define GBK 16

__global__ __launch_bounds__(256) void gemm_nt(const float* __restrict__ A,
                                               const float* __restrict__ B,
                                               float* __restrict__ C,
                                               int M, int N, int K)
{
    __shared__ float As[GBK][GBM + 4];
    __shared__ float Bs[GBK][GBN + 4];

    const int tid = threadIdx.x;
    const int ty  = tid >> 4;
    const int tx  = tid & 15;
    const int m0  = blockIdx.y * GBM;
    const int n0  = blockIdx.x * GBN;

    const float* Aptr = A + (size_t)m0 * K;
    const float* Bptr = B + (size_t)n0 * K;

    float acc[8][8];
#pragma unroll
    for (int i = 0; i < 8; i++)
#pragma unroll
        for (int j = 0; j < 8; j++) acc[i][j] = 0.0f;

    for (int k0 = 0; k0 < K; k0 += GBK) {
#pragma unroll
        for (int it = 0; it < 2; it++) {
            int li  = tid + it * 256;
            int row = li >> 2;            // 0..127
            int cs  = (li & 3) << 2;      // 0,4,8,12
            float4 av = *(const float4*)(Aptr + (size_t)row * K + k0 + cs);
            As[cs + 0][row] = av.x; As[cs + 1][row] = av.y;
            As[cs + 2][row] = av.z; As[cs + 3][row] = av.w;
            float4 bv = *(const float4*)(Bptr + (size_t)row * K + k0 + cs);
            Bs[cs + 0][row] = bv.x; Bs[cs + 1][row] = bv.y;
            Bs[cs + 2][row] = bv.z; Bs[cs + 3][row] = bv.w;
        }
        __syncthreads();

#pragma unroll
        for (int kk = 0; kk < GBK; kk++) {
            float a[8], b[8];
            *(float4*)&a[0] = *(const float4*)&As[kk][ty * 8];
            *(float4*)&a[4] = *(const float4*)&As[kk][ty * 8 + 4];
            *(float4*)&b[0] = *(const float4*)&Bs[kk][tx * 8];
            *(float4*)&b[4] = *(const float4*)&Bs[kk][tx * 8 + 4];
#pragma unroll
            for (int i = 0; i < 8; i++)
#pragma unroll
                for (int j = 0; j < 8; j++)
                    acc[i][j] += a[i] * b[j];
        }
        __syncthreads();
    }

#pragma unroll
    for (int i = 0; i < 8; i++) {
        float* Crow = C + (size_t)(m0 + ty * 8 + i) * N + n0 + tx * 8;
        *(float4*)(Crow)     = make_float4(acc[i][0], acc[i][1], acc[i][2], acc[i][3]);
        *(float4*)(Crow + 4) = make_float4(acc[i][4], acc[i][5], acc[i][6], acc[i][7]);
    }
}

// =================================================================
// per-head RMSNorm + RoPE (in place).  One block = one (s, head) row.
// =================================================================
__global__ __launch_bounds__(128) void norm_rope(float* __restrict__ X,
                                                 const float* __restrict__ w,
                                                 const float* __restrict__ cosv,
                                                 const float* __restrict__ sinv,
                                                 int heads)
{
    const int h = blockIdx.x % heads;
    const int s = blockIdx.x / heads;
    float* row = X + ((size_t)s * heads + h) * HD;
    const int d = threadIdx.x;

    float x  = row[d];
    float ss = x * x;
#pragma unroll
    for (int off = 16; off > 0; off >>= 1)
        ss += __shfl_xor_sync(0xffffffffu, ss, off);

    __shared__ float sb[4];
    const int warp = d >> 5, lane = d & 31;
    if (lane == 0) sb[warp] = ss;
    __syncthreads();
    float tot = sb[0] + sb[1] + sb[2] + sb[3];
    float xn  = x * rsqrtf(tot * (1.0f / HD) + 1e-6f) * w[d];

    __shared__ float xs[HD];
    xs[d] = xn;
    __syncthreads();
    float other = (d < HD / 2) ? -xs[d + HD / 2] : xs[d - HD / 2];
    row[d] = xn * cosv[(size_t)s * HD + d] + other * sinv[(size_t)s * HD + d];
}

// =================================================================
// Causal flash attention.  Q tile 128 rows x D=128, K tile 64 x 128.
// Q/K stored d-chunk-major as float4 (odd float4-strides -> conflict-free
// transpose stores AND fragment loads).  V stored row-major float4.
// 256 threads, 16x16 grid: S micro-tile 8x4, O micro-tile 8x8.
// =================================================================
#define FBM 128
#define FBN 64
#define NDC 32      // 128 / 4 d-chunks
#define QP  129     // float4 row stride (odd)
#define KP  65
#define VP  33
#define PP  68      // float row stride for P

#define FLASH_SMEM ((NDC*QP + NDC*KP + FBN*VP) * 16 + FBM * PP * 4)

__global__ __launch_bounds__(256) void flash_kernel(const float* __restrict__ Q,
                                                    const float* __restrict__ K,
                                                    const float* __restrict__ V,
                                                    float* __restrict__ O)
{
    extern __shared__ float4 sm4[];
    float4* Qs = sm4;
    float4* Ks = Qs + NDC * QP;
    float4* Vs = Ks + NDC * KP;
    float*  Ps = (float*)(Vs + FBN * VP);

    const int tid = threadIdx.x;
    const int ty  = tid >> 4;
    const int tx  = tid & 15;
    const int h   = blockIdx.y;
    // heavy q-tiles first (better tail with causal imbalance)
    const int q0  = ((int)gridDim.x - 1 - (int)blockIdx.x) * FBM;
    const int kvh = h >> 1;   // H/KV = 2

    const float* Qb = Q + (size_t)h * HD;
    const float* Kb = K + (size_t)kvh * HD;
    const float* Vb = V + (size_t)kvh * HD;

    // ---- load Q tile (transposed to d-chunk-major) ----
#pragma unroll
    for (int it = 0; it < 16; it++) {
        int li = tid + it * 256;
        int r  = li >> 5;          // 0..127
        int dc = li & 31;          // 0..31
        Qs[dc * QP + r] = *(const float4*)(Qb + (size_t)(q0 + r) * (NH * HD) + dc * 4);
    }

    float m_i[8], l_i[8], o_acc[8][8];
#pragma unroll
    for (int i = 0; i < 8; i++) {
        m_i[i] = -1e30f;
        l_i[i] = 0.0f;
#pragma unroll
        for (int j = 0; j < 8; j++) o_acc[i][j] = 0.0f;
    }

    const int   ktiles = q0 / FBN + 2;
    const float scale  = 0.08838834764831845f;   // 1/sqrt(128)

    for (int kt = 0; kt < ktiles; kt++) {
        const int k0 = kt * FBN;

        // ---- load K (transposed), V (row-major) ----
#pragma unroll
        for (int it = 0; it < 8; it++) {
            int li = tid + it * 256;
            int r  = li >> 5;      // 0..63
            int dc = li & 31;
            Ks[dc * KP + r] = *(const float4*)(Kb + (size_t)(k0 + r) * (NKV * HD) + dc * 4);
            Vs[r * VP + dc] = *(const float4*)(Vb + (size_t)(k0 + r) * (NKV * HD) + dc * 4);
        }
        __syncthreads();

        // ---- S = Q K^T  (8 rows x 4 cols per thread) ----
        float sc[8][4];
#pragma unroll
        for (int i = 0; i < 8; i++)
#pragma unroll
            for (int j = 0; j < 4; j++) sc[i][j] = 0.0f;

#pragma unroll 2
        for (int dc = 0; dc < NDC; dc++) {
            float4 b0 = Ks[dc * KP + tx * 4 + 0];
            float4 b1 = Ks[dc * KP + tx * 4 + 1];
            float4 b2 = Ks[dc * KP + tx * 4 + 2];
            float4 b3 = Ks[dc * KP + tx * 4 + 3];
#pragma unroll
            for (int i = 0; i < 8; i++) {
                float4 a = Qs[dc * QP + ty * 8 + i];
                sc[i][0] += a.x * b0.x + a.y * b0.y + a.z * b0.z + a.w * b0.w;
                sc[i][1] += a.x * b1.x + a.y * b1.y + a.z * b1.z + a.w * b1.w;
                sc[i][2] += a.x * b2.x + a.y * b2.y + a.z * b2.z + a.w * b2.w;
                sc[i][3] += a.x * b3.x + a.y * b3.y + a.z * b3.z + a.w * b3.w;
            }
        }

        // ---- scale + causal mask ----
        if (k0 + FBN - 1 > q0) {
#pragma unroll
            for (int i = 0; i < 8; i++) {
                int row = q0 + ty * 8 + i;
#pragma unroll
                for (int j = 0; j < 4; j++) {
                    int col = k0 + tx * 4 + j;
                    sc[i][j] = (col > row) ? -1e30f : sc[i][j] * scale;
                }
            }
        } else {
#pragma unroll
            for (int i = 0; i < 8; i++)
#pragma unroll
                for (int j = 0; j < 4; j++) sc[i][j] *= scale;
        }

        // ---- online softmax (row stats reduced across the 16 tx lanes) ----
#pragma unroll
        for (int i = 0; i < 8; i++) {
            float rm = fmaxf(fmaxf(sc[i][0], sc[i][1]), fmaxf(sc[i][2], sc[i][3]));
#pragma unroll
            for (int off = 1; off < 16; off <<= 1)
                rm = fmaxf(rm, __shfl_xor_sync(0xffffffffu, rm, off));
            float mnew  = fmaxf(m_i[i], rm);
            float alpha = __expf(m_i[i] - mnew);
            float p0 = __expf(sc[i][0] - mnew);
            float p1 = __expf(sc[i][1] - mnew);
            float p2 = __expf(sc[i][2] - mnew);
            float p3 = __expf(sc[i][3] - mnew);
            float rs = p0 + p1 + p2 + p3;
#pragma unroll
            for (int off = 1; off < 16; off <<= 1)
                rs += __shfl_xor_sync(0xffffffffu, rs, off);
            l_i[i] = l_i[i] * alpha + rs;
            m_i[i] = mnew;
#pragma unroll
            for (int j = 0; j < 8; j++) o_acc[i][j] *= alpha;
            *(float4*)&Ps[(ty * 8 + i) * PP + tx * 4] = make_float4(p0, p1, p2, p3);
        }
        __syncthreads();

        // ---- O += P V  (8 rows x 8 cols per thread) ----
#pragma unroll 4
        for (int kk = 0; kk < FBN; kk++) {
            float4 v0 = Vs[kk * VP + tx * 2];
            float4 v1 = Vs[kk * VP + tx * 2 + 1];
#pragma unroll
            for (int i = 0; i < 8; i++) {
                float p = Ps[(ty * 8 + i) * PP + kk];
                o_acc[i][0] += p * v0.x; o_acc[i][1] += p * v0.y;
                o_acc[i][2] += p * v0.z; o_acc[i][3] += p * v0.w;
                o_acc[i][4] += p * v1.x; o_acc[i][5] += p * v1.y;
                o_acc[i][6] += p * v1.z; o_acc[i][7] += p * v1.w;
            }
        }
        __syncthreads();   // protect Ks/Vs/Ps for next tile's loads
    }

    // ---- epilogue ----
#pragma unroll
    for (int i = 0; i < 8; i++) {
        float inv = 1.0f / l_i[i];
        float* Orow = O + (size_t)(q0 + ty * 8 + i) * (NH * HD) + h * HD + tx * 8;
        *(float4*)(Orow)     = make_float4(o_acc[i][0] * inv, o_acc[i][1] * inv,
                                           o_acc[i][2] * inv, o_acc[i][3] * inv);
        *(float4*)(Orow + 4) = make_float4(o_acc[i][4] * inv, o_acc[i][5] * inv,
                                           o_acc[i][6] * inv, o_acc[i][7] * inv);
    }
}

// =================================================================
// launch
// =================================================================
extern "C" void kernel_launch(void* const* d_in, const int* in_sizes, int n_in,
                              void* d_out, int out_size)
{
    const float* hs   = (const float*)d_in[0];   // (1,4096,2048)
    const float* cosv = (const float*)d_in[1];   // (1,4096,128)
    const float* sinv = (const float*)d_in[2];
    const float* wq   = (const float*)d_in[3];   // (2048,2048)
    const float* wk   = (const float*)d_in[4];   // (1024,2048)
    const float* wv   = (const float*)d_in[5];   // (1024,2048)
    const float* wo   = (const float*)d_in[6];   // (2048,2048)
    const float* qw   = (const float*)d_in[7];   // (128,)
    const float* kw   = (const float*)d_in[8];   // (128,)
    float* out = (float*)d_out;

    float *Qp, *Kp, *Vp, *AOp;
    cudaGetSymbolAddress((void**)&Qp,  g_Q);
    cudaGetSymbolAddress((void**)&Kp,  g_K);
    cudaGetSymbolAddress((void**)&Vp,  g_V);
    cudaGetSymbolAddress((void**)&AOp, g_AO);

    cudaFuncSetAttribute(flash_kernel,
                         cudaFuncAttributeMaxDynamicSharedMemorySize, FLASH_SMEM);

    // QKV projections
    gemm_nt<<<dim3((NH * HD) / GBN, SEQ / GBM), 256>>>(hs, wq, Qp, SEQ, NH * HD, HID);
    gemm_nt<<<dim3((NKV * HD) / GBN, SEQ / GBM), 256>>>(hs, wk, Kp, SEQ, NKV * HD, HID);
    gemm_nt<<<dim3((NKV * HD) / GBN, SEQ / GBM), 256>>>(hs, wv, Vp, SEQ, NKV * HD, HID);

    // RMSNorm + RoPE (Q, K)
    norm_rope<<<SEQ * NH,  128>>>(Qp, qw, cosv, sinv, NH);
    norm_rope<<<SEQ * NKV, 128>>>(Kp, kw, cosv, sinv, NKV);

    // causal flash attention (GQA)
    flash_kernel<<<dim3(SEQ / FBM, NH), 256, FLASH_SMEM>>>(Qp, Kp, Vp, AOp);

    // output projection
    gemm_nt<<<dim3(HID / GBN, SEQ / GBM), 256>>>(AOp, wo, out, SEQ, HID, HID);
}

// round 3
// speedup vs baseline: 2.9956x; 2.9956x over previous
#include <cuda_runtime.h>
#include <math.h>
#include <stdint.h>

#define SEQ   4096
#define HID   2048
#define NH    16
#define NKV   8
#define HD    128

// ---------------- scratch (no allocation allowed) ----------------
__device__ float g_Q [SEQ * NH  * HD];
__device__ float g_K [SEQ * NKV * HD];
__device__ float g_V [SEQ * NKV * HD];
__device__ float g_AO[SEQ * NH  * HD];
__device__ float g_HS[SEQ * HID];
__device__ float g_WQ[NH  * HD * HID];
__device__ float g_WK[NKV * HD * HID];
__device__ float g_WV[NKV * HD * HID];
__device__ float g_WO[HID * NH * HD];

// ---------------- PTX helpers ----------------
__device__ __forceinline__ void mma_tf32(float& d0, float& d1, float& d2, float& d3,
                                         uint32_t a0, uint32_t a1, uint32_t a2, uint32_t a3,
                                         uint32_t b0, uint32_t b1)
{
    asm volatile(
        "mma.sync.aligned.m16n8k8.row.col.f32.tf32.tf32.f32 "
        "{%0,%1,%2,%3},{%4,%5,%6,%7},{%8,%9},{%0,%1,%2,%3};\n"
        : "+f"(d0), "+f"(d1), "+f"(d2), "+f"(d3)
        : "r"(a0), "r"(a1), "r"(a2), "r"(a3), "r"(b0), "r"(b1));
}
__device__ __forceinline__ uint32_t f2tf(float f)
{
    uint32_t r;
    asm("cvt.rna.tf32.f32 %0, %1;" : "=r"(r) : "f"(f));
    return r;
}
__device__ __forceinline__ void cp_async16(void* smem, const void* gmem)
{
    uint32_t s = (uint32_t)__cvta_generic_to_shared(smem);
    asm volatile("cp.async.cg.shared.global [%0], [%1], 16;\n" :: "r"(s), "l"(gmem));
}
#define CP_COMMIT()  asm volatile("cp.async.commit_group;\n")
#define CP_WAIT(n)   asm volatile("cp.async.wait_group %0;\n" :: "n"(n))

// =================================================================
// tf32 rounding pass (float4 vectorized)
// =================================================================
__global__ __launch_bounds__(256) void tf32_round4(const float4* __restrict__ in,
                                                   float4* __restrict__ out, int n4)
{
    int i = blockIdx.x * blockDim.x + threadIdx.x;
    if (i < n4) {
        float4 v = in[i];
        v.x = __uint_as_float(f2tf(v.x));
        v.y = __uint_as_float(f2tf(v.y));
        v.z = __uint_as_float(f2tf(v.z));
        v.w = __uint_as_float(f2tf(v.w));
        out[i] = v;
    }
}

// =================================================================
// tf32 tensor-core NT GEMM: C[M,N] = A[M,K] * B[N,K]^T
// 128x128 block tile, BK=32, 256 threads (8 warps, 4x2),
// warp tile 32x64, mma m16n8k8, cp.async double buffering.
// =================================================================
#define TBM 128
#define TBN 128
#define TBK 32
#define TAS 36
#define GEMM_SMEM (2 * 2 * TBM * TAS * 4)

__global__ __launch_bounds__(256) void gemm_nt_tc(const float* __restrict__ A,
                                                  const float* __restrict__ B,
                                                  float* __restrict__ C,
                                                  int M, int N, int K)
{
    extern __shared__ float sg[];
    float* As = sg;
    float* Bs = sg + 2 * TBM * TAS;

    const int tid  = threadIdx.x;
    const int w    = tid >> 5, lane = tid & 31;
    const int wm   = w >> 1,   wn   = w & 1;
    const int q    = lane >> 2, t = lane & 3;
    const int m0   = blockIdx.y * TBM;
    const int n0   = blockIdx.x * TBN;

    float acc[2][8][4];
#pragma unroll
    for (int mt = 0; mt < 2; mt++)
#pragma unroll
        for (int nt = 0; nt < 8; nt++)
#pragma unroll
            for (int c = 0; c < 4; c++) acc[mt][nt][c] = 0.0f;

    const int T = K / TBK;

    auto load_stage = [&](int k0, int st) {
        float* as = As + st * TBM * TAS;
        float* bs = Bs + st * TBM * TAS;
#pragma unroll
        for (int it = 0; it < 4; it++) {
            int li  = tid + it * 256;
            int row = li >> 3;
            int cs  = (li & 7) * 4;
            cp_async16(as + row * TAS + cs, A + (size_t)(m0 + row) * K + k0 + cs);
            cp_async16(bs + row * TAS + cs, B + (size_t)(n0 + row) * K + k0 + cs);
        }
        CP_COMMIT();
    };

    load_stage(0, 0);

    for (int ti = 0; ti < T; ti++) {
        const int st = ti & 1;
        if (ti + 1 < T) { load_stage((ti + 1) * TBK, st ^ 1); CP_WAIT(1); }
        else            { CP_WAIT(0); }
        __syncthreads();

        const float* as = As + st * TBM * TAS;
        const float* bs = Bs + st * TBM * TAS;

#pragma unroll
        for (int ks = 0; ks < 4; ks++) {
            const int k = ks * 8;
            uint32_t af[2][4], bf[8][2];
#pragma unroll
            for (int mt = 0; mt < 2; mt++) {
                const float* ap = as + (wm * 32 + mt * 16) * TAS + k;
                af[mt][0] = __float_as_uint(ap[q * TAS + t]);
                af[mt][1] = __float_as_uint(ap[(q + 8) * TAS + t]);
                af[mt][2] = __float_as_uint(ap[q * TAS + t + 4]);
                af[mt][3] = __float_as_uint(ap[(q + 8) * TAS + t + 4]);
            }
#pragma unroll
            for (int nt = 0; nt < 8; nt++) {
                const float* bp = bs + (wn * 64 + nt * 8) * TAS + k;
                bf[nt][0] = __float_as_uint(bp[q * TAS + t]);
                bf[nt][1] = __float_as_uint(bp[q * TAS + t + 4]);
            }
#pragma unroll
            for (int mt = 0; mt < 2; mt++)
#pragma unroll
                for (int nt = 0; nt < 8; nt++)
                    mma_tf32(acc[mt][nt][0], acc[mt][nt][1], acc[mt][nt][2], acc[mt][nt][3],
                             af[mt][0], af[mt][1], af[mt][2], af[mt][3],
                             bf[nt][0], bf[nt][1]);
        }
        __syncthreads();
    }

#pragma unroll
    for (int mt = 0; mt < 2; mt++) {
        const int row = m0 + wm * 32 + mt * 16 + q;
#pragma unroll
        for (int nt = 0; nt < 8; nt++) {
            const int col = n0 + wn * 64 + nt * 8 + 2 * t;
            *(float2*)(C + (size_t)row * N + col)       = make_float2(acc[mt][nt][0], acc[mt][nt][1]);
            *(float2*)(C + (size_t)(row + 8) * N + col) = make_float2(acc[mt][nt][2], acc[mt][nt][3]);
        }
    }
}

// =================================================================
// per-head RMSNorm + RoPE (in place), output rounded to tf32.
// =================================================================
__global__ __launch_bounds__(128) void norm_rope(float* __restrict__ X,
                                                 const float* __restrict__ w,
                                                 const float* __restrict__ cosv,
                                                 const float* __restrict__ sinv,
                                                 int heads, float outscale)
{
    const int h = blockIdx.x % heads;
    const int s = blockIdx.x / heads;
    float* row = X + ((size_t)s * heads + h) * HD;
    const int d = threadIdx.x;

    float x  = row[d];
    float ss = x * x;
#pragma unroll
    for (int off = 16; off > 0; off >>= 1)
        ss += __shfl_xor_sync(0xffffffffu, ss, off);

    __shared__ float sb[4];
    const int warp = d >> 5, lane = d & 31;
    if (lane == 0) sb[warp] = ss;
    __syncthreads();
    float tot = sb[0] + sb[1] + sb[2] + sb[3];
    float xn  = x * rsqrtf(tot * (1.0f / HD) + 1e-6f) * w[d];

    __shared__ float xs[HD];
    xs[d] = xn;
    __syncthreads();
    float other = (d < HD / 2) ? -xs[d + HD / 2] : xs[d - HD / 2];
    float res = (xn * cosv[(size_t)s * HD + d] + other * sinv[(size_t)s * HD + d]) * outscale;
    row[d] = __uint_as_float(f2tf(res));
}

// =================================================================
// Causal flash attention (tf32 tensor cores).
// Q tile 128 x 128, K/V tile 64 keys. 256 threads, 8 warps x 1:
// each warp owns 16 FULL rows (all 64 keys) -> softmax stats warp-local.
// S warp tile 16x64, O warp tile 16x128.
// =================================================================
#define FQ   128
#define FK   64
#define DSTR 132   // 128+4 : row-indexed frags conflict-free
#define VSTR 136   // 128+8 : k-indexed V frags conflict-free
#define PSTR 68    // 64+4
#define FLASH_SMEM ((FQ*DSTR + FK*DSTR + FK*VSTR + FQ*PSTR) * 4)

__global__ __launch_bounds__(256) void flash_tc(const float* __restrict__ Q,
                                                const float* __restrict__ K,
                                                const float* __restrict__ V,
                                                float* __restrict__ O)
{
    extern __shared__ float sf[];
    float* Qs = sf;                 // [128][132]
    float* Ks = Qs + FQ * DSTR;     // [64][132]
    float* Vs = Ks + FK * DSTR;     // [64][136]
    float* Ps = Vs + FK * VSTR;     // [128][68]

    const int tid  = threadIdx.x;
    const int w    = tid >> 5, lane = tid & 31;
    const int q    = lane >> 2, t = lane & 3;
    const int h    = blockIdx.y;
    const int q0   = ((int)gridDim.x - 1 - (int)blockIdx.x) * FQ;  // heavy tiles first
    const int kvh  = h >> 1;
    const int r0   = w * 16;       // this warp's row base within the tile

    const float* Qb = Q + (size_t)h   * HD;
    const float* Kb = K + (size_t)kvh * HD;
    const float* Vb = V + (size_t)kvh * HD;

    // ---- load Q tile [128][128] into smem ----
#pragma unroll
    for (int it = 0; it < 16; it++) {
        int li = tid + it * 256;
        int r  = li >> 5;
        int dc = (li & 31) * 4;
        *(float4*)(Qs + r * DSTR + dc) =
            *(const float4*)(Qb + (size_t)(q0 + r) * (NH * HD) + dc);
    }

    float o[16][4];
    float m_i[2], l_i[2];
#pragma unroll
    for (int hf = 0; hf < 2; hf++) { m_i[hf] = -1e30f; l_i[hf] = 0.0f; }
#pragma unroll
    for (int nt = 0; nt < 16; nt++)
#pragma unroll
        for (int c = 0; c < 4; c++) o[nt][c] = 0.0f;

    const int ktiles = q0 / FK + 2;

    for (int kt = 0; kt < ktiles; kt++) {
        const int k0 = kt * FK;

        __syncthreads();   // all warps done reading Ks/Vs from previous tile
#pragma unroll
        for (int it = 0; it < 8; it++) {
            int li = tid + it * 256;
            int r  = li >> 5;
            int dc = (li & 31) * 4;
            cp_async16(Ks + r * DSTR + dc, Kb + (size_t)(k0 + r) * (NKV * HD) + dc);
            cp_async16(Vs + r * VSTR + dc, Vb + (size_t)(k0 + r) * (NKV * HD) + dc);
        }
        CP_COMMIT(); CP_WAIT(0);
        __syncthreads();

        // ---- S = Q K^T : warp tile 16 rows x 64 keys ----
        float s[8][4];
#pragma unroll
        for (int nt = 0; nt < 8; nt++)
#pragma unroll
            for (int c = 0; c < 4; c++) s[nt][c] = 0.0f;

#pragma unroll
        for (int ks = 0; ks < 16; ks++) {
            const int k = ks * 8;
            uint32_t af[4], bf[8][2];
            const float* ap = Qs + r0 * DSTR + k;
            af[0] = __float_as_uint(ap[q * DSTR + t]);
            af[1] = __float_as_uint(ap[(q + 8) * DSTR + t]);
            af[2] = __float_as_uint(ap[q * DSTR + t + 4]);
            af[3] = __float_as_uint(ap[(q + 8) * DSTR + t + 4]);
#pragma unroll
            for (int nt = 0; nt < 8; nt++) {
                const float* bp = Ks + nt * 8 * DSTR + k;
                bf[nt][0] = __float_as_uint(bp[q * DSTR + t]);
                bf[nt][1] = __float_as_uint(bp[q * DSTR + t + 4]);
            }
#pragma unroll
            for (int nt = 0; nt < 8; nt++)
                mma_tf32(s[nt][0], s[nt][1], s[nt][2], s[nt][3],
                         af[0], af[1], af[2], af[3], bf[nt][0], bf[nt][1]);
        }

        // ---- causal mask (last two tiles only) ----
        if (k0 + FK - 1 > q0) {
#pragma unroll
            for (int hf = 0; hf < 2; hf++) {
                const int row = q0 + r0 + q + hf * 8;
#pragma unroll
                for (int nt = 0; nt < 8; nt++) {
                    const int col = k0 + nt * 8 + 2 * t;
                    if (col     > row) s[nt][hf * 2]     = -1e30f;
                    if (col + 1 > row) s[nt][hf * 2 + 1] = -1e30f;
                }
            }
        }

        // ---- online softmax: stats fully warp-local (all 64 keys here) ----
#pragma unroll
        for (int hf = 0; hf < 2; hf++) {
            float rm = -1e30f;
#pragma unroll
            for (int nt = 0; nt < 8; nt++)
                rm = fmaxf(rm, fmaxf(s[nt][hf * 2], s[nt][hf * 2 + 1]));
            rm = fmaxf(rm, __shfl_xor_sync(0xffffffffu, rm, 1));
            rm = fmaxf(rm, __shfl_xor_sync(0xffffffffu, rm, 2));

            const float mnew  = fmaxf(m_i[hf], rm);
            const float alpha = __expf(m_i[hf] - mnew);
            float rs = 0.0f;
            const int prow = (r0 + q + hf * 8) * PSTR;
#pragma unroll
            for (int nt = 0; nt < 8; nt++) {
                float p0 = __expf(s[nt][hf * 2]     - mnew);
                float p1 = __expf(s[nt][hf * 2 + 1] - mnew);
                p0 = __uint_as_float(f2tf(p0));   // round, and sum the ROUNDED P
                p1 = __uint_as_float(f2tf(p1));
                rs += p0 + p1;
                *(float2*)(Ps + prow + nt * 8 + 2 * t) = make_float2(p0, p1);
            }
            rs += __shfl_xor_sync(0xffffffffu, rs, 1);
            rs += __shfl_xor_sync(0xffffffffu, rs, 2);

            l_i[hf] = l_i[hf] * alpha + rs;
            m_i[hf] = mnew;
#pragma unroll
            for (int nt = 0; nt < 16; nt++) {
                o[nt][hf * 2]     *= alpha;
                o[nt][hf * 2 + 1] *= alpha;
            }
        }
        __syncwarp();   // P rows are warp-private: warp-level visibility suffices

        // ---- O += P V : warp tile 16 rows x 128 d-cols, K = 64 keys ----
#pragma unroll
        for (int ks = 0; ks < 8; ks++) {
            const int k = ks * 8;
            uint32_t af[4];
            const float* ap = Ps + r0 * PSTR + k;
            af[0] = __float_as_uint(ap[q * PSTR + t]);
            af[1] = __float_as_uint(ap[(q + 8) * PSTR + t]);
            af[2] = __float_as_uint(ap[q * PSTR + t + 4]);
            af[3] = __float_as_uint(ap[(q + 8) * PSTR + t + 4]);
#pragma unroll
            for (int nt = 0; nt < 16; nt++) {
                const float* bp = Vs + k * VSTR + nt * 8;
                uint32_t b0 = __float_as_uint(bp[t * VSTR + q]);
                uint32_t b1 = __float_as_uint(bp[(t + 4) * VSTR + q]);
                mma_tf32(o[nt][0], o[nt][1], o[nt][2], o[nt][3],
                         af[0], af[1], af[2], af[3], b0, b1);
            }
        }
    }

    // ---- epilogue: normalize, round to tf32 (wo-GEMM input), store ----
#pragma unroll
    for (int hf = 0; hf < 2; hf++) {
        const float inv = 1.0f / l_i[hf];
        const int row = q0 + r0 + q + hf * 8;
        float* Orow = O + (size_t)row * (NH * HD) + h * HD;
#pragma unroll
        for (int nt = 0; nt < 16; nt++) {
            const int col = nt * 8 + 2 * t;
            float v0 = __uint_as_float(f2tf(o[nt][hf * 2]     * inv));
            float v1 = __uint_as_float(f2tf(o[nt][hf * 2 + 1] * inv));
            *(float2*)(Orow + col) = make_float2(v0, v1);
        }
    }
}

// =================================================================
// launch
// =================================================================
extern "C" void kernel_launch(void* const* d_in, const int* in_sizes, int n_in,
                              void* d_out, int out_size)
{
    const float* hs   = (const float*)d_in[0];
    const float* cosv = (const float*)d_in[1];
    const float* sinv = (const float*)d_in[2];
    const float* wq   = (const float*)d_in[3];
    const float* wk   = (const float*)d_in[4];
    const float* wv   = (const float*)d_in[5];
    const float* wo   = (const float*)d_in[6];
    const float* qw   = (const float*)d_in[7];
    const float* kw   = (const float*)d_in[8];
    float* out = (float*)d_out;

    float *Qp, *Kp, *Vp, *AOp, *HSp, *WQp, *WKp, *WVp, *WOp;
    cudaGetSymbolAddress((void**)&Qp,  g_Q);
    cudaGetSymbolAddress((void**)&Kp,  g_K);
    cudaGetSymbolAddress((void**)&Vp,  g_V);
    cudaGetSymbolAddress((void**)&AOp, g_AO);
    cudaGetSymbolAddress((void**)&HSp, g_HS);
    cudaGetSymbolAddress((void**)&WQp, g_WQ);
    cudaGetSymbolAddress((void**)&WKp, g_WK);
    cudaGetSymbolAddress((void**)&WVp, g_WV);
    cudaGetSymbolAddress((void**)&WOp, g_WO);

    cudaFuncSetAttribute(gemm_nt_tc, cudaFuncAttributeMaxDynamicSharedMemorySize, GEMM_SMEM);
    cudaFuncSetAttribute(flash_tc,   cudaFuncAttributeMaxDynamicSharedMemorySize, FLASH_SMEM);

    const int RB = 256;
    tf32_round4<<<(SEQ*HID/4 + RB-1)/RB, RB>>>((const float4*)hs, (float4*)HSp, SEQ*HID/4);
    tf32_round4<<<(NH*HD*HID/4 + RB-1)/RB, RB>>>((const float4*)wq, (float4*)WQp, NH*HD*HID/4);
    tf32_round4<<<(NKV*HD*HID/4 + RB-1)/RB, RB>>>((const float4*)wk, (float4*)WKp, NKV*HD*HID/4);
    tf32_round4<<<(NKV*HD*HID/4 + RB-1)/RB, RB>>>((const float4*)wv, (float4*)WVp, NKV*HD*HID/4);
    tf32_round4<<<(HID*NH*HD/4 + RB-1)/RB, RB>>>((const float4*)wo, (float4*)WOp, HID*NH*HD/4);

    gemm_nt_tc<<<dim3((NH*HD)/TBN,  SEQ/TBM), 256, GEMM_SMEM>>>(HSp, WQp, Qp, SEQ, NH*HD,  HID);
    gemm_nt_tc<<<dim3((NKV*HD)/TBN, SEQ/TBM), 256, GEMM_SMEM>>>(HSp, WKp, Kp, SEQ, NKV*HD, HID);
    gemm_nt_tc<<<dim3((NKV*HD)/TBN, SEQ/TBM), 256, GEMM_SMEM>>>(HSp, WVp, Vp, SEQ, NKV*HD, HID);

    tf32_round4<<<(SEQ*NKV*HD/4 + RB-1)/RB, RB>>>((const float4*)Vp, (float4*)Vp, SEQ*NKV*HD/4);

    norm_rope<<<SEQ * NH,  128>>>(Qp, qw, cosv, sinv, NH,  0.08838834764831845f);
    norm_rope<<<SEQ * NKV, 128>>>(Kp, kw, cosv, sinv, NKV, 1.0f);

    flash_tc<<<dim3(SEQ / FQ, NH), 256, FLASH_SMEM>>>(Qp, Kp, Vp, AOp);

    gemm_nt_tc<<<dim3(HID/TBN, SEQ/TBM), 256, GEMM_SMEM>>>(AOp, WOp, out, SEQ, HID, HID);
}

// round 5
// speedup vs baseline: 3.6798x; 1.2284x over previous
#include <cuda_runtime.h>
#include <math.h>
#include <stdint.h>

#define SEQ   4096
#define HID   2048
#define NH    16
#define NKV   8
#define HD    128

// ---------------- scratch (no allocation allowed) ----------------
__device__ float g_Q [SEQ * NH  * HD];
__device__ float g_K [SEQ * NKV * HD];
__device__ float g_V [SEQ * NKV * HD];
__device__ float g_AO[SEQ * NH  * HD];
__device__ float g_HS[SEQ * HID];
__device__ float g_WQ[NH  * HD * HID];
__device__ float g_WK[NKV * HD * HID];
__device__ float g_WV[NKV * HD * HID];
__device__ float g_WO[HID * NH * HD];

// ---------------- PTX helpers ----------------
__device__ __forceinline__ void mma_tf32(float& d0, float& d1, float& d2, float& d3,
                                         uint32_t a0, uint32_t a1, uint32_t a2, uint32_t a3,
                                         uint32_t b0, uint32_t b1)
{
    asm volatile(
        "mma.sync.aligned.m16n8k8.row.col.f32.tf32.tf32.f32 "
        "{%0,%1,%2,%3},{%4,%5,%6,%7},{%8,%9},{%0,%1,%2,%3};\n"
        : "+f"(d0), "+f"(d1), "+f"(d2), "+f"(d3)
        : "r"(a0), "r"(a1), "r"(a2), "r"(a3), "r"(b0), "r"(b1));
}
__device__ __forceinline__ uint32_t f2tf(float f)
{
    uint32_t r;
    asm("cvt.rna.tf32.f32 %0, %1;" : "=r"(r) : "f"(f));
    return r;
}
__device__ __forceinline__ float ex2f(float x)
{
    float r;
    asm("ex2.approx.ftz.f32 %0, %1;" : "=f"(r) : "f"(x));
    return r;
}
__device__ __forceinline__ void cp_async16(void* smem, const void* gmem)
{
    uint32_t s = (uint32_t)__cvta_generic_to_shared(smem);
    asm volatile("cp.async.cg.shared.global [%0], [%1], 16;\n" :: "r"(s), "l"(gmem));
}
#define CP_COMMIT()  asm volatile("cp.async.commit_group;\n")
#define CP_WAIT(n)   asm volatile("cp.async.wait_group %0;\n" :: "n"(n))

// =================================================================
// tf32 rounding pass (float4 vectorized)
// =================================================================
__global__ __launch_bounds__(256) void tf32_round4(const float4* __restrict__ in,
                                                   float4* __restrict__ out, int n4)
{
    int i = blockIdx.x * blockDim.x + threadIdx.x;
    if (i < n4) {
        float4 v = in[i];
        v.x = __uint_as_float(f2tf(v.x));
        v.y = __uint_as_float(f2tf(v.y));
        v.z = __uint_as_float(f2tf(v.z));
        v.w = __uint_as_float(f2tf(v.w));
        out[i] = v;
    }
}

// =================================================================
// tf32 tensor-core NT GEMM (mma.sync): C[M,N] = A[M,K] * B[N,K]^T
// 128x128 tile, BK=32, 256 threads (8 warps, 4x2), warp tile 32x64.
// round_out: round C to tf32 in epilogue (for V).
// =================================================================
#define TBM 128
#define TBN 128
#define TBK 32
#define TAS 36
#define GEMM_SMEM (2 * 2 * TBM * TAS * 4)

__global__ __launch_bounds__(256) void gemm_nt_tc(const float* __restrict__ A,
                                                  const float* __restrict__ B,
                                                  float* __restrict__ C,
                                                  int M, int N, int K, int round_out)
{
    extern __shared__ float sg[];
    float* As = sg;
    float* Bs = sg + 2 * TBM * TAS;

    const int tid  = threadIdx.x;
    const int w    = tid >> 5, lane = tid & 31;
    const int wm   = w >> 1,   wn   = w & 1;
    const int q    = lane >> 2, t = lane & 3;
    const int m0   = blockIdx.y * TBM;
    const int n0   = blockIdx.x * TBN;

    float acc[2][8][4];
#pragma unroll
    for (int mt = 0; mt < 2; mt++)
#pragma unroll
        for (int nt = 0; nt < 8; nt++)
#pragma unroll
            for (int c = 0; c < 4; c++) acc[mt][nt][c] = 0.0f;

    const int T = K / TBK;

    auto load_stage = [&](int k0, int st) {
        float* as = As + st * TBM * TAS;
        float* bs = Bs + st * TBM * TAS;
#pragma unroll
        for (int it = 0; it < 4; it++) {
            int li  = tid + it * 256;
            int row = li >> 3;
            int cs  = (li & 7) * 4;
            cp_async16(as + row * TAS + cs, A + (size_t)(m0 + row) * K + k0 + cs);
            cp_async16(bs + row * TAS + cs, B + (size_t)(n0 + row) * K + k0 + cs);
        }
        CP_COMMIT();
    };

    load_stage(0, 0);

    for (int ti = 0; ti < T; ti++) {
        const int st = ti & 1;
        if (ti + 1 < T) { load_stage((ti + 1) * TBK, st ^ 1); CP_WAIT(1); }
        else            { CP_WAIT(0); }
        __syncthreads();

        const float* as = As + st * TBM * TAS;
        const float* bs = Bs + st * TBM * TAS;

#pragma unroll
        for (int ks = 0; ks < 4; ks++) {
            const int k = ks * 8;
            uint32_t af[2][4], bf[8][2];
#pragma unroll
            for (int mt = 0; mt < 2; mt++) {
                const float* ap = as + (wm * 32 + mt * 16) * TAS + k;
                af[mt][0] = __float_as_uint(ap[q * TAS + t]);
                af[mt][1] = __float_as_uint(ap[(q + 8) * TAS + t]);
                af[mt][2] = __float_as_uint(ap[q * TAS + t + 4]);
                af[mt][3] = __float_as_uint(ap[(q + 8) * TAS + t + 4]);
            }
#pragma unroll
            for (int nt = 0; nt < 8; nt++) {
                const float* bp = bs + (wn * 64 + nt * 8) * TAS + k;
                bf[nt][0] = __float_as_uint(bp[q * TAS + t]);
                bf[nt][1] = __float_as_uint(bp[q * TAS + t + 4]);
            }
#pragma unroll
            for (int mt = 0; mt < 2; mt++)
#pragma unroll
                for (int nt = 0; nt < 8; nt++)
                    mma_tf32(acc[mt][nt][0], acc[mt][nt][1], acc[mt][nt][2], acc[mt][nt][3],
                             af[mt][0], af[mt][1], af[mt][2], af[mt][3],
                             bf[nt][0], bf[nt][1]);
        }
        __syncthreads();
    }

    if (round_out) {
#pragma unroll
        for (int mt = 0; mt < 2; mt++)
#pragma unroll
            for (int nt = 0; nt < 8; nt++)
#pragma unroll
                for (int c = 0; c < 4; c++)
                    acc[mt][nt][c] = __uint_as_float(f2tf(acc[mt][nt][c]));
    }

#pragma unroll
    for (int mt = 0; mt < 2; mt++) {
        const int row = m0 + wm * 32 + mt * 16 + q;
#pragma unroll
        for (int nt = 0; nt < 8; nt++) {
            const int col = n0 + wn * 64 + nt * 8 + 2 * t;
            *(float2*)(C + (size_t)row * N + col)       = make_float2(acc[mt][nt][0], acc[mt][nt][1]);
            *(float2*)(C + (size_t)(row + 8) * N + col) = make_float2(acc[mt][nt][2], acc[mt][nt][3]);
        }
    }
}

// =================================================================
// per-head RMSNorm + RoPE (in place), output rounded to tf32.
// =================================================================
__global__ __launch_bounds__(128) void norm_rope(float* __restrict__ X,
                                                 const float* __restrict__ w,
                                                 const float* __restrict__ cosv,
                                                 const float* __restrict__ sinv,
                                                 int heads, float outscale)
{
    const int h = blockIdx.x % heads;
    const int s = blockIdx.x / heads;
    float* row = X + ((size_t)s * heads + h) * HD;
    const int d = threadIdx.x;

    float x  = row[d];
    float ss = x * x;
#pragma unroll
    for (int off = 16; off > 0; off >>= 1)
        ss += __shfl_xor_sync(0xffffffffu, ss, off);

    __shared__ float sb[4];
    const int warp = d >> 5, lane = d & 31;
    if (lane == 0) sb[warp] = ss;
    __syncthreads();
    float tot = sb[0] + sb[1] + sb[2] + sb[3];
    float xn  = x * rsqrtf(tot * (1.0f / HD) + 1e-6f) * w[d];

    __shared__ float xs[HD];
    xs[d] = xn;
    __syncthreads();
    float other = (d < HD / 2) ? -xs[d + HD / 2] : xs[d - HD / 2];
    float res = (xn * cosv[(size_t)s * HD + d] + other * sinv[(size_t)s * HD + d]) * outscale;
    row[d] = __uint_as_float(f2tf(res));
}

// =================================================================
// Causal flash attention (tf32 mma.sync), v2:
//  - Q fragments in registers (loaded once)
//  - double-buffered K/V via cp.async (prefetch next tile during compute)
//  - exp2-domain softmax (log2e folded into Q scale), raw EX2
//  - warp-uniform O-rescale skip
// 256 threads, 8 warps, warp tile 16 rows x all 64 keys / 128 d.
// =================================================================
#define FQ   128
#define FK   64
#define DSTR 132   // row-indexed frags conflict-free
#define VSTR 136   // k-indexed V frags conflict-free
#define PSTR 68
#define KVSTG (FK * DSTR + FK * VSTR)     // 17152 floats per stage
#define FLASH_SMEM ((FQ * PSTR + 2 * KVSTG) * 4)   // 172032 B

__global__ __launch_bounds__(256) void flash_tc(const float* __restrict__ Q,
                                                const float* __restrict__ K,
                                                const float* __restrict__ V,
                                                float* __restrict__ O)
{
    extern __shared__ float sf[];
    float* Ps    = sf;                      // [128][68]
    float* stage = sf + FQ * PSTR;          // 2 x (K [64][132] + V [64][136])

    const int tid  = threadIdx.x;
    const int w    = tid >> 5, lane = tid & 31;
    const int q    = lane >> 2, t = lane & 3;
    const int h    = blockIdx.y;
    const int q0   = ((int)gridDim.x - 1 - (int)blockIdx.x) * FQ;  // heavy tiles first
    const int kvh  = h >> 1;
    const int r0   = w * 16;

    const float* Qb = Q + (size_t)h   * HD;
    const float* Kb = K + (size_t)kvh * HD;
    const float* Vb = V + (size_t)kvh * HD;

    // ---- stage Q through smem (stage area), extract fragments to registers ----
    uint32_t qf[16][4];
    {
        float* Qs = stage;
#pragma unroll
        for (int it = 0; it < 16; it++) {
            int li = tid + it * 256;
            int r  = li >> 5;
            int dc = (li & 31) * 4;
            *(float4*)(Qs + r * DSTR + dc) =
                *(const float4*)(Qb + (size_t)(q0 + r) * (NH * HD) + dc);
        }
        __syncthreads();
#pragma unroll
        for (int ks = 0; ks < 16; ks++) {
            const float* ap = Qs + r0 * DSTR + ks * 8;
            qf[ks][0] = __float_as_uint(ap[q * DSTR + t]);
            qf[ks][1] = __float_as_uint(ap[(q + 8) * DSTR + t]);
            qf[ks][2] = __float_as_uint(ap[q * DSTR + t + 4]);
            qf[ks][3] = __float_as_uint(ap[(q + 8) * DSTR + t + 4]);
        }
        __syncthreads();    // everyone extracted before stage reuse
    }

    float o[16][4];
    float m_i[2], l_i[2];
#pragma unroll
    for (int hf = 0; hf < 2; hf++) { m_i[hf] = -1e30f; l_i[hf] = 0.0f; }
#pragma unroll
    for (int nt = 0; nt < 16; nt++)
#pragma unroll
        for (int c = 0; c < 4; c++) o[nt][c] = 0.0f;

    const int ktiles = q0 / FK + 2;

    auto prefetch = [&](int kt, int st) {
        float* Ks = stage + st * KVSTG;
        float* Vs = Ks + FK * DSTR;
        const int k0 = kt * FK;
#pragma unroll
        for (int it = 0; it < 8; it++) {
            int li = tid + it * 256;
            int r  = li >> 5;
            int dc = (li & 31) * 4;
            cp_async16(Ks + r * DSTR + dc, Kb + (size_t)(k0 + r) * (NKV * HD) + dc);
            cp_async16(Vs + r * VSTR + dc, Vb + (size_t)(k0 + r) * (NKV * HD) + dc);
        }
        CP_COMMIT();
    };

    prefetch(0, 0);

    for (int kt = 0; kt < ktiles; kt++) {
        const int st = kt & 1;
        const int k0 = kt * FK;

        if (kt + 1 < ktiles) { prefetch(kt + 1, st ^ 1); CP_WAIT(1); }
        else                 { CP_WAIT(0); }
        __syncthreads();     // stage st data visible to all

        const float* Ks = stage + st * KVSTG;
        const float* Vs = Ks + FK * DSTR;

        // ---- S = Q K^T : 16 rows x 64 keys per warp (Q from registers) ----
        float s[8][4];
#pragma unroll
        for (int nt = 0; nt < 8; nt++)
#pragma unroll
            for (int c = 0; c < 4; c++) s[nt][c] = 0.0f;

#pragma unroll
        for (int ks = 0; ks < 16; ks++) {
            const int k = ks * 8;
            uint32_t bf[8][2];
#pragma unroll
            for (int nt = 0; nt < 8; nt++) {
                const float* bp = Ks + nt * 8 * DSTR + k;
                bf[nt][0] = __float_as_uint(bp[q * DSTR + t]);
                bf[nt][1] = __float_as_uint(bp[q * DSTR + t + 4]);
            }
#pragma unroll
            for (int nt = 0; nt < 8; nt++)
                mma_tf32(s[nt][0], s[nt][1], s[nt][2], s[nt][3],
                         qf[ks][0], qf[ks][1], qf[ks][2], qf[ks][3],
                         bf[nt][0], bf[nt][1]);
        }

        // ---- causal mask ----
        if (k0 + FK - 1 > q0) {
#pragma unroll
            for (int hf = 0; hf < 2; hf++) {
                const int row = q0 + r0 + q + hf * 8;
#pragma unroll
                for (int nt = 0; nt < 8; nt++) {
                    const int col = k0 + nt * 8 + 2 * t;
                    if (col     > row) s[nt][hf * 2]     = -1e30f;
                    if (col + 1 > row) s[nt][hf * 2 + 1] = -1e30f;
                }
            }
        }

        // ---- online softmax in exp2 domain (scale*log2e folded into Q) ----
#pragma unroll
        for (int hf = 0; hf < 2; hf++) {
            float rm = -1e30f;
#pragma unroll
            for (int nt = 0; nt < 8; nt++)
                rm = fmaxf(rm, fmaxf(s[nt][hf * 2], s[nt][hf * 2 + 1]));
            rm = fmaxf(rm, __shfl_xor_sync(0xffffffffu, rm, 1));
            rm = fmaxf(rm, __shfl_xor_sync(0xffffffffu, rm, 2));

            const float mnew  = fmaxf(m_i[hf], rm);
            const float alpha = ex2f(m_i[hf] - mnew);    // exactly 1.0 when unchanged
            float rs = 0.0f;
            const int prow = (r0 + q + hf * 8) * PSTR;
#pragma unroll
            for (int nt = 0; nt < 8; nt++) {
                float p0 = ex2f(s[nt][hf * 2]     - mnew);
                float p1 = ex2f(s[nt][hf * 2 + 1] - mnew);
                p0 = __uint_as_float(f2tf(p0));   // round; l sums the ROUNDED P
                p1 = __uint_as_float(f2tf(p1));
                rs += p0 + p1;
                *(float2*)(Ps + prow + nt * 8 + 2 * t) = make_float2(p0, p1);
            }
            rs += __shfl_xor_sync(0xffffffffu, rs, 1);
            rs += __shfl_xor_sync(0xffffffffu, rs, 2);

            l_i[hf] = l_i[hf] * alpha + rs;
            m_i[hf] = mnew;

            if (__any_sync(0xffffffffu, alpha != 1.0f)) {
#pragma unroll
                for (int nt = 0; nt < 16; nt++) {
                    o[nt][hf * 2]     *= alpha;
                    o[nt][hf * 2 + 1] *= alpha;
                }
            }
        }
        __syncwarp();   // P rows warp-private

        // ---- O += P V : 16 rows x 128 d, K = 64 keys ----
#pragma unroll
        for (int ks = 0; ks < 8; ks++) {
            const int k = ks * 8;
            uint32_t af[4];
            const float* ap = Ps + r0 * PSTR + k;
            af[0] = __float_as_uint(ap[q * PSTR + t]);
            af[1] = __float_as_uint(ap[(q + 8) * PSTR + t]);
            af[2] = __float_as_uint(ap[q * PSTR + t + 4]);
            af[3] = __float_as_uint(ap[(q + 8) * PSTR + t + 4]);
#pragma unroll
            for (int nt = 0; nt < 16; nt++) {
                const float* bp = Vs + k * VSTR + nt * 8;
                uint32_t b0 = __float_as_uint(bp[t * VSTR + q]);
                uint32_t b1 = __float_as_uint(bp[(t + 4) * VSTR + q]);
                mma_tf32(o[nt][0], o[nt][1], o[nt][2], o[nt][3],
                         af[0], af[1], af[2], af[3], b0, b1);
            }
        }
        __syncthreads();   // all warps done with stage st before it's refilled
    }

    // ---- epilogue ----
#pragma unroll
    for (int hf = 0; hf < 2; hf++) {
        const float inv = 1.0f / l_i[hf];
        const int row = q0 + r0 + q + hf * 8;
        float* Orow = O + (size_t)row * (NH * HD) + h * HD;
#pragma unroll
        for (int nt = 0; nt < 16; nt++) {
            const int col = nt * 8 + 2 * t;
            float v0 = __uint_as_float(f2tf(o[nt][hf * 2]     * inv));
            float v1 = __uint_as_float(f2tf(o[nt][hf * 2 + 1] * inv));
            *(float2*)(Orow + col) = make_float2(v0, v1);
        }
    }
}

// =================================================================
// launch
// =================================================================
extern "C" void kernel_launch(void* const* d_in, const int* in_sizes, int n_in,
                              void* d_out, int out_size)
{
    const float* hs   = (const float*)d_in[0];
    const float* cosv = (const float*)d_in[1];
    const float* sinv = (const float*)d_in[2];
    const float* wq   = (const float*)d_in[3];
    const float* wk   = (const float*)d_in[4];
    const float* wv   = (const float*)d_in[5];
    const float* wo   = (const float*)d_in[6];
    const float* qw   = (const float*)d_in[7];
    const float* kw   = (const float*)d_in[8];
    float* out = (float*)d_out;

    float *Qp, *Kp, *Vp, *AOp, *HSp, *WQp, *WKp, *WVp, *WOp;
    cudaGetSymbolAddress((void**)&Qp,  g_Q);
    cudaGetSymbolAddress((void**)&Kp,  g_K);
    cudaGetSymbolAddress((void**)&Vp,  g_V);
    cudaGetSymbolAddress((void**)&AOp, g_AO);
    cudaGetSymbolAddress((void**)&HSp, g_HS);
    cudaGetSymbolAddress((void**)&WQp, g_WQ);
    cudaGetSymbolAddress((void**)&WKp, g_WK);
    cudaGetSymbolAddress((void**)&WVp, g_WV);
    cudaGetSymbolAddress((void**)&WOp, g_WO);

    cudaFuncSetAttribute(gemm_nt_tc, cudaFuncAttributeMaxDynamicSharedMemorySize, GEMM_SMEM);
    cudaFuncSetAttribute(flash_tc,   cudaFuncAttributeMaxDynamicSharedMemorySize, FLASH_SMEM);

    const int RB = 256;
    tf32_round4<<<(SEQ*HID/4 + RB-1)/RB, RB>>>((const float4*)hs, (float4*)HSp, SEQ*HID/4);
    tf32_round4<<<(NH*HD*HID/4 + RB-1)/RB, RB>>>((const float4*)wq, (float4*)WQp, NH*HD*HID/4);
    tf32_round4<<<(NKV*HD*HID/4 + RB-1)/RB, RB>>>((const float4*)wk, (float4*)WKp, NKV*HD*HID/4);
    tf32_round4<<<(NKV*HD*HID/4 + RB-1)/RB, RB>>>((const float4*)wv, (float4*)WVp, NKV*HD*HID/4);
    tf32_round4<<<(HID*NH*HD/4 + RB-1)/RB, RB>>>((const float4*)wo, (float4*)WOp, HID*NH*HD/4);

    // QKV projections (V rounded to tf32 in epilogue)
    gemm_nt_tc<<<dim3((NH*HD)/TBN,  SEQ/TBM), 256, GEMM_SMEM>>>(HSp, WQp, Qp, SEQ, NH*HD,  HID, 0);
    gemm_nt_tc<<<dim3((NKV*HD)/TBN, SEQ/TBM), 256, GEMM_SMEM>>>(HSp, WKp, Kp, SEQ, NKV*HD, HID, 0);
    gemm_nt_tc<<<dim3((NKV*HD)/TBN, SEQ/TBM), 256, GEMM_SMEM>>>(HSp, WVp, Vp, SEQ, NKV*HD, HID, 1);

    // RMSNorm + RoPE; fold attention scale * log2(e) into Q (exp2-domain softmax)
    norm_rope<<<SEQ * NH,  128>>>(Qp, qw, cosv, sinv, NH,
                                  0.08838834764831845f * 1.4426950408889634f);
    norm_rope<<<SEQ * NKV, 128>>>(Kp, kw, cosv, sinv, NKV, 1.0f);

    flash_tc<<<dim3(SEQ / FQ, NH), 256, FLASH_SMEM>>>(Qp, Kp, Vp, AOp);

    gemm_nt_tc<<<dim3(HID/TBN, SEQ/TBM), 256, GEMM_SMEM>>>(AOp, WOp, out, SEQ, HID, HID, 0);
}

// round 6
// speedup vs baseline: 6.6093x; 1.7961x over previous
#include <cuda_runtime.h>
#include <cuda_fp16.h>
#include <math.h>
#include <stdint.h>

#define SEQ   4096
#define HID   2048
#define NH    16
#define NKV   8
#define HD    128

// ---------------- scratch (no allocation allowed) ----------------
__device__ float  g_Qf [SEQ * NH  * HD];           // fp32 Q (pre-norm)
__device__ float  g_Kf [SEQ * NKV * HD];           // fp32 K (pre-norm)
__device__ __half g_HS16[SEQ * HID];
__device__ __half g_WQ16[NH  * HD * HID];
__device__ __half g_WK16[NKV * HD * HID];
__device__ __half g_WV16[NKV * HD * HID];
__device__ __half g_WO16[HID * NH * HD];
__device__ __half g_Q16 [SEQ * NH  * HD];
__device__ __half g_K16 [SEQ * NKV * HD];
__device__ __half g_VT16[NKV * HD * SEQ];          // V transposed: [kv*d][s]
__device__ __half g_AO16[SEQ * NH  * HD];

// ---------------- PTX helpers ----------------
__device__ __forceinline__ void mma_f16(float& d0, float& d1, float& d2, float& d3,
                                        uint32_t a0, uint32_t a1, uint32_t a2, uint32_t a3,
                                        uint32_t b0, uint32_t b1)
{
    asm volatile(
        "mma.sync.aligned.m16n8k16.row.col.f32.f16.f16.f32 "
        "{%0,%1,%2,%3},{%4,%5,%6,%7},{%8,%9},{%0,%1,%2,%3};\n"
        : "+f"(d0), "+f"(d1), "+f"(d2), "+f"(d3)
        : "r"(a0), "r"(a1), "r"(a2), "r"(a3), "r"(b0), "r"(b1));
}
__device__ __forceinline__ float ex2f(float x)
{
    float r;
    asm("ex2.approx.ftz.f32 %0, %1;" : "=f"(r) : "f"(x));
    return r;
}
__device__ __forceinline__ uint32_t packh2(float lo, float hi)
{
    __half2 h = __floats2half2_rn(lo, hi);   // .x = lo (low 16 bits)
    return *(uint32_t*)&h;
}
__device__ __forceinline__ void cp_async16(void* smem, const void* gmem)
{
    uint32_t s = (uint32_t)__cvta_generic_to_shared(smem);
    asm volatile("cp.async.cg.shared.global [%0], [%1], 16;\n" :: "r"(s), "l"(gmem));
}
#define CP_COMMIT()  asm volatile("cp.async.commit_group;\n")
#define CP_WAIT(n)   asm volatile("cp.async.wait_group %0;\n" :: "n"(n))

// =================================================================
// fp32 -> fp16 convert (vectorized)
// =================================================================
__global__ __launch_bounds__(256) void cvt_h(const float4* __restrict__ in,
                                             __half2* __restrict__ out, int n4)
{
    int i = blockIdx.x * blockDim.x + threadIdx.x;
    if (i < n4) {
        float4 v = in[i];
        out[2 * i]     = __floats2half2_rn(v.x, v.y);
        out[2 * i + 1] = __floats2half2_rn(v.z, v.w);
    }
}

// =================================================================
// fp16 tensor-core NT GEMM (m16n8k16): C[M,N] = A[M,K] * B[N,K]^T
// 128x128 tile, BK=64, 256 threads (8 warps, 4x2), warp tile 32x64.
// out_half: 0 -> fp32 C, 1 -> fp16 C.
// =================================================================
#define TBM 128
#define TBN 128
#define TBK 64
#define TAS 72        // halves per smem row (36 words, 36%8==4 -> conflict-free)
#define GSTG (2 * TBM * TAS)                // halves per stage (A+B)
#define GEMM_SMEM (2 * GSTG * 2)            // bytes

__global__ __launch_bounds__(256) void gemm_h(const __half* __restrict__ A,
                                              const __half* __restrict__ B,
                                              void* __restrict__ Cv,
                                              int M, int N, int K, int out_half)
{
    extern __shared__ __half sh[];

    const int tid  = threadIdx.x;
    const int w    = tid >> 5, lane = tid & 31;
    const int wm   = w >> 1,   wn   = w & 1;
    const int q    = lane >> 2, t = lane & 3;
    const int m0   = blockIdx.y * TBM;
    const int n0   = blockIdx.x * TBN;

    float acc[2][8][4];
#pragma unroll
    for (int mt = 0; mt < 2; mt++)
#pragma unroll
        for (int nt = 0; nt < 8; nt++)
#pragma unroll
            for (int c = 0; c < 4; c++) acc[mt][nt][c] = 0.0f;

    const int T = K / TBK;

    auto load_stage = [&](int k0, int st) {
        __half* as = sh + st * GSTG;
        __half* bs = as + TBM * TAS;
#pragma unroll
        for (int it = 0; it < 4; it++) {
            int li  = tid + it * 256;
            int row = li >> 3;
            int c   = (li & 7) * 8;
            cp_async16(as + row * TAS + c, A + (size_t)(m0 + row) * K + k0 + c);
        }
#pragma unroll
        for (int it = 0; it < 4; it++) {
            int li  = tid + it * 256;
            int row = li >> 3;
            int c   = (li & 7) * 8;
            cp_async16(bs + row * TAS + c, B + (size_t)(n0 + row) * K + k0 + c);
        }
        CP_COMMIT();
    };

    load_stage(0, 0);

    for (int ti = 0; ti < T; ti++) {
        const int st = ti & 1;
        if (ti + 1 < T) { load_stage((ti + 1) * TBK, st ^ 1); CP_WAIT(1); }
        else            { CP_WAIT(0); }
        __syncthreads();

        const __half* as = sh + st * GSTG;
        const __half* bs = as + TBM * TAS;

#pragma unroll
        for (int ks = 0; ks < 4; ks++) {
            const int k = ks * 16;
            uint32_t af[2][4], bf[8][2];
#pragma unroll
            for (int mt = 0; mt < 2; mt++) {
                const __half* ap = as + (wm * 32 + mt * 16) * TAS + k;
                af[mt][0] = *(const uint32_t*)(ap + q * TAS + 2 * t);
                af[mt][1] = *(const uint32_t*)(ap + (q + 8) * TAS + 2 * t);
                af[mt][2] = *(const uint32_t*)(ap + q * TAS + 2 * t + 8);
                af[mt][3] = *(const uint32_t*)(ap + (q + 8) * TAS + 2 * t + 8);
            }
#pragma unroll
            for (int nt = 0; nt < 8; nt++) {
                const __half* bp = bs + (wn * 64 + nt * 8 + q) * TAS + k;
                bf[nt][0] = *(const uint32_t*)(bp + 2 * t);
                bf[nt][1] = *(const uint32_t*)(bp + 2 * t + 8);
            }
#pragma unroll
            for (int mt = 0; mt < 2; mt++)
#pragma unroll
                for (int nt = 0; nt < 8; nt++)
                    mma_f16(acc[mt][nt][0], acc[mt][nt][1], acc[mt][nt][2], acc[mt][nt][3],
                            af[mt][0], af[mt][1], af[mt][2], af[mt][3],
                            bf[nt][0], bf[nt][1]);
        }
        __syncthreads();
    }

    if (out_half) {
        __half* C = (__half*)Cv;
#pragma unroll
        for (int mt = 0; mt < 2; mt++) {
            const int row = m0 + wm * 32 + mt * 16 + q;
#pragma unroll
            for (int nt = 0; nt < 8; nt++) {
                const int col = n0 + wn * 64 + nt * 8 + 2 * t;
                *(uint32_t*)(C + (size_t)row * N + col)       = packh2(acc[mt][nt][0], acc[mt][nt][1]);
                *(uint32_t*)(C + (size_t)(row + 8) * N + col) = packh2(acc[mt][nt][2], acc[mt][nt][3]);
            }
        }
    } else {
        float* C = (float*)Cv;
#pragma unroll
        for (int mt = 0; mt < 2; mt++) {
            const int row = m0 + wm * 32 + mt * 16 + q;
#pragma unroll
            for (int nt = 0; nt < 8; nt++) {
                const int col = n0 + wn * 64 + nt * 8 + 2 * t;
                *(float2*)(C + (size_t)row * N + col)       = make_float2(acc[mt][nt][0], acc[mt][nt][1]);
                *(float2*)(C + (size_t)(row + 8) * N + col) = make_float2(acc[mt][nt][2], acc[mt][nt][3]);
            }
        }
    }
}

// =================================================================
// per-head RMSNorm + RoPE: fp32 in -> fp16 out (separate arrays).
// =================================================================
__global__ __launch_bounds__(128) void norm_rope_h(const float* __restrict__ X,
                                                   __half* __restrict__ Y,
                                                   const float* __restrict__ w,
                                                   const float* __restrict__ cosv,
                                                   const float* __restrict__ sinv,
                                                   int heads, float outscale)
{
    const int h = blockIdx.x % heads;
    const int s = blockIdx.x / heads;
    const float* row = X + ((size_t)s * heads + h) * HD;
    __half* out = Y + ((size_t)s * heads + h) * HD;
    const int d = threadIdx.x;

    float x  = row[d];
    float ss = x * x;
#pragma unroll
    for (int off = 16; off > 0; off >>= 1)
        ss += __shfl_xor_sync(0xffffffffu, ss, off);

    __shared__ float sb[4];
    const int warp = d >> 5, lane = d & 31;
    if (lane == 0) sb[warp] = ss;
    __syncthreads();
    float tot = sb[0] + sb[1] + sb[2] + sb[3];
    float xn  = x * rsqrtf(tot * (1.0f / HD) + 1e-6f) * w[d];

    __shared__ float xs[HD];
    xs[d] = xn;
    __syncthreads();
    float other = (d < HD / 2) ? -xs[d + HD / 2] : xs[d - HD / 2];
    float res = (xn * cosv[(size_t)s * HD + d] + other * sinv[(size_t)s * HD + d]) * outscale;
    out[d] = __float2half_rn(res);
}

// =================================================================
// Causal flash attention, fp16 m16n8k16:
//  - Q fragments in registers; P stays in registers (accum->half2 pack)
//  - V consumed pre-transposed ([d][s]) so PV B-frags are contiguous
//  - double-buffered K/V, exp2 softmax, rescale skip
// 256 threads, 8 warps, warp tile 16 rows x 64 keys / 128 d.
// =================================================================
#define FQ   128
#define FK   64
#define KSTR 136            // halves (68 words, %8==4)
#define VTSTR 72            // halves (36 words, %8==4)
#define QSTR 136
#define KVSTG (FK * KSTR + FQ * VTSTR)      // halves per stage = 17920
#define FLASH_SMEM (2 * KVSTG * 2)          // 71680 B

__global__ __launch_bounds__(256) void flash_h(const __half* __restrict__ Q,
                                               const __half* __restrict__ K,
                                               const __half* __restrict__ VT,
                                               __half* __restrict__ O)
{
    extern __shared__ __half sh[];

    const int tid  = threadIdx.x;
    const int w    = tid >> 5, lane = tid & 31;
    const int q    = lane >> 2, t = lane & 3;
    const int h    = blockIdx.y;
    const int q0   = ((int)gridDim.x - 1 - (int)blockIdx.x) * FQ;  // heavy tiles first
    const int kvh  = h >> 1;
    const int r0   = w * 16;

    const __half* Qb  = Q  + (size_t)h * HD;
    const __half* Kb  = K  + (size_t)kvh * HD;
    const __half* VTb = VT + (size_t)(kvh * HD) * SEQ;

    // ---- stage Q in stage0 area, extract fragments to registers ----
    uint32_t qf[8][4];
    {
        __half* Qs = sh;
#pragma unroll
        for (int it = 0; it < 8; it++) {
            int li = tid + it * 256;
            int r  = li >> 4;
            int c  = (li & 15) * 8;
            *(float4*)(Qs + r * QSTR + c) =
                *(const float4*)(Qb + (size_t)(q0 + r) * (NH * HD) + c);
        }
        __syncthreads();
#pragma unroll
        for (int ks = 0; ks < 8; ks++) {
            const __half* ap = Qs + r0 * QSTR + ks * 16;
            qf[ks][0] = *(const uint32_t*)(ap + q * QSTR + 2 * t);
            qf[ks][1] = *(const uint32_t*)(ap + (q + 8) * QSTR + 2 * t);
            qf[ks][2] = *(const uint32_t*)(ap + q * QSTR + 2 * t + 8);
            qf[ks][3] = *(const uint32_t*)(ap + (q + 8) * QSTR + 2 * t + 8);
        }
        __syncthreads();
    }

    float o[16][4];
    float m_i[2], l_i[2];
#pragma unroll
    for (int hf = 0; hf < 2; hf++) { m_i[hf] = -1e30f; l_i[hf] = 0.0f; }
#pragma unroll
    for (int nt = 0; nt < 16; nt++)
#pragma unroll
        for (int c = 0; c < 4; c++) o[nt][c] = 0.0f;

    const int ktiles = q0 / FK + 2;

    auto prefetch = [&](int kt, int st) {
        __half* Ks = sh + st * KVSTG;
        __half* Vs = Ks + FK * KSTR;
        const int k0 = kt * FK;
        // K tile [64][128] halves
#pragma unroll
        for (int it = 0; it < 4; it++) {
            int li = tid + it * 256;
            int r  = li >> 4;
            int c  = (li & 15) * 8;
            cp_async16(Ks + r * KSTR + c, Kb + (size_t)(k0 + r) * (NKV * HD) + c);
        }
        // Vt tile [128 d][64 keys] halves
#pragma unroll
        for (int it = 0; it < 4; it++) {
            int li = tid + it * 256;
            int r  = li >> 3;
            int c  = (li & 7) * 8;
            cp_async16(Vs + r * VTSTR + c, VTb + (size_t)r * SEQ + k0 + c);
        }
        CP_COMMIT();
    };

    prefetch(0, 0);

    for (int kt = 0; kt < ktiles; kt++) {
        const int st = kt & 1;
        const int k0 = kt * FK;

        if (kt + 1 < ktiles) { prefetch(kt + 1, st ^ 1); CP_WAIT(1); }
        else                 { CP_WAIT(0); }
        __syncthreads();

        const __half* Ks = sh + st * KVSTG;
        const __half* Vs = Ks + FK * KSTR;

        // ---- S = Q K^T : 16 rows x 64 keys per warp, Q from registers ----
        float s[8][4];
#pragma unroll
        for (int nt = 0; nt < 8; nt++)
#pragma unroll
            for (int c = 0; c < 4; c++) s[nt][c] = 0.0f;

#pragma unroll
        for (int ks = 0; ks < 8; ks++) {
            const int k = ks * 16;
            uint32_t bf[8][2];
#pragma unroll
            for (int nt = 0; nt < 8; nt++) {
                const __half* bp = Ks + (nt * 8 + q) * KSTR + k;
                bf[nt][0] = *(const uint32_t*)(bp + 2 * t);
                bf[nt][1] = *(const uint32_t*)(bp + 2 * t + 8);
            }
#pragma unroll
            for (int nt = 0; nt < 8; nt++)
                mma_f16(s[nt][0], s[nt][1], s[nt][2], s[nt][3],
                        qf[ks][0], qf[ks][1], qf[ks][2], qf[ks][3],
                        bf[nt][0], bf[nt][1]);
        }

        // ---- causal mask ----
        if (k0 + FK - 1 > q0) {
#pragma unroll
            for (int hf = 0; hf < 2; hf++) {
                const int row = q0 + r0 + q + hf * 8;
#pragma unroll
                for (int nt = 0; nt < 8; nt++) {
                    const int col = k0 + nt * 8 + 2 * t;
                    if (col     > row) s[nt][hf * 2]     = -1e30f;
                    if (col + 1 > row) s[nt][hf * 2 + 1] = -1e30f;
                }
            }
        }

        // ---- online softmax (exp2 domain), P written back into s[] ----
#pragma unroll
        for (int hf = 0; hf < 2; hf++) {
            float rm = -1e30f;
#pragma unroll
            for (int nt = 0; nt < 8; nt++)
                rm = fmaxf(rm, fmaxf(s[nt][hf * 2], s[nt][hf * 2 + 1]));
            rm = fmaxf(rm, __shfl_xor_sync(0xffffffffu, rm, 1));
            rm = fmaxf(rm, __shfl_xor_sync(0xffffffffu, rm, 2));

            const float mnew  = fmaxf(m_i[hf], rm);
            const float alpha = ex2f(m_i[hf] - mnew);
            float rs = 0.0f;
#pragma unroll
            for (int nt = 0; nt < 8; nt++) {
                float p0 = ex2f(s[nt][hf * 2]     - mnew);
                float p1 = ex2f(s[nt][hf * 2 + 1] - mnew);
                rs += p0 + p1;
                s[nt][hf * 2]     = p0;
                s[nt][hf * 2 + 1] = p1;
            }
            rs += __shfl_xor_sync(0xffffffffu, rs, 1);
            rs += __shfl_xor_sync(0xffffffffu, rs, 2);

            l_i[hf] = l_i[hf] * alpha + rs;
            m_i[hf] = mnew;

            if (__any_sync(0xffffffffu, alpha != 1.0f)) {
#pragma unroll
                for (int nt = 0; nt < 16; nt++) {
                    o[nt][hf * 2]     *= alpha;
                    o[nt][hf * 2 + 1] *= alpha;
                }
            }
        }

        // ---- pack P accumulator -> fp16 A-fragments (no smem!) ----
        uint32_t paf[4][4];
#pragma unroll
        for (int j = 0; j < 4; j++) {
            paf[j][0] = packh2(s[2 * j][0],     s[2 * j][1]);
            paf[j][1] = packh2(s[2 * j][2],     s[2 * j][3]);
            paf[j][2] = packh2(s[2 * j + 1][0], s[2 * j + 1][1]);
            paf[j][3] = packh2(s[2 * j + 1][2], s[2 * j + 1][3]);
        }

        // ---- O += P V : 16 rows x 128 d, K = 64 keys (Vt [d][key]) ----
#pragma unroll
        for (int j = 0; j < 4; j++) {
            const int k = j * 16;
#pragma unroll
            for (int nt = 0; nt < 16; nt++) {
                const __half* bp = Vs + (nt * 8 + q) * VTSTR + k;
                uint32_t b0 = *(const uint32_t*)(bp + 2 * t);
                uint32_t b1 = *(const uint32_t*)(bp + 2 * t + 8);
                mma_f16(o[nt][0], o[nt][1], o[nt][2], o[nt][3],
                        paf[j][0], paf[j][1], paf[j][2], paf[j][3], b0, b1);
            }
        }
        __syncthreads();   // all warps done with stage st before refill
    }

    // ---- epilogue: normalize, store fp16 ----
#pragma unroll
    for (int hf = 0; hf < 2; hf++) {
        const float inv = 1.0f / l_i[hf];
        const int row = q0 + r0 + q + hf * 8;
        __half* Orow = O + (size_t)row * (NH * HD) + h * HD;
#pragma unroll
        for (int nt = 0; nt < 16; nt++) {
            const int col = nt * 8 + 2 * t;
            *(uint32_t*)(Orow + col) = packh2(o[nt][hf * 2] * inv, o[nt][hf * 2 + 1] * inv);
        }
    }
}

// =================================================================
// launch
// =================================================================
extern "C" void kernel_launch(void* const* d_in, const int* in_sizes, int n_in,
                              void* d_out, int out_size)
{
    const float* hs   = (const float*)d_in[0];
    const float* cosv = (const float*)d_in[1];
    const float* sinv = (const float*)d_in[2];
    const float* wq   = (const float*)d_in[3];
    const float* wk   = (const float*)d_in[4];
    const float* wv   = (const float*)d_in[5];
    const float* wo   = (const float*)d_in[6];
    const float* qw   = (const float*)d_in[7];
    const float* kw   = (const float*)d_in[8];
    float* out = (float*)d_out;

    float *Qfp, *Kfp;
    __half *HSp, *WQp, *WKp, *WVp, *WOp, *Q16p, *K16p, *VTp, *AOp;
    cudaGetSymbolAddress((void**)&Qfp,  g_Qf);
    cudaGetSymbolAddress((void**)&Kfp,  g_Kf);
    cudaGetSymbolAddress((void**)&HSp,  g_HS16);
    cudaGetSymbolAddress((void**)&WQp,  g_WQ16);
    cudaGetSymbolAddress((void**)&WKp,  g_WK16);
    cudaGetSymbolAddress((void**)&WVp,  g_WV16);
    cudaGetSymbolAddress((void**)&WOp,  g_WO16);
    cudaGetSymbolAddress((void**)&Q16p, g_Q16);
    cudaGetSymbolAddress((void**)&K16p, g_K16);
    cudaGetSymbolAddress((void**)&VTp,  g_VT16);
    cudaGetSymbolAddress((void**)&AOp,  g_AO16);

    cudaFuncSetAttribute(gemm_h,  cudaFuncAttributeMaxDynamicSharedMemorySize, GEMM_SMEM);
    cudaFuncSetAttribute(flash_h, cudaFuncAttributeMaxDynamicSharedMemorySize, FLASH_SMEM);

    const int RB = 256;
    cvt_h<<<(SEQ*HID/4 + RB-1)/RB, RB>>>((const float4*)hs, (__half2*)HSp, SEQ*HID/4);
    cvt_h<<<(NH*HD*HID/4 + RB-1)/RB, RB>>>((const float4*)wq, (__half2*)WQp, NH*HD*HID/4);
    cvt_h<<<(NKV*HD*HID/4 + RB-1)/RB, RB>>>((const float4*)wk, (__half2*)WKp, NKV*HD*HID/4);
    cvt_h<<<(NKV*HD*HID/4 + RB-1)/RB, RB>>>((const float4*)wv, (__half2*)WVp, NKV*HD*HID/4);
    cvt_h<<<(HID*NH*HD/4 + RB-1)/RB, RB>>>((const float4*)wo, (__half2*)WOp, HID*NH*HD/4);

    // Q, K projections -> fp32 (for norm); V^T = WV * HS^T -> fp16 directly
    gemm_h<<<dim3((NH*HD)/TBN,  SEQ/TBM), 256, GEMM_SMEM>>>(HSp, WQp, Qfp, SEQ, NH*HD,  HID, 0);
    gemm_h<<<dim3((NKV*HD)/TBN, SEQ/TBM), 256, GEMM_SMEM>>>(HSp, WKp, Kfp, SEQ, NKV*HD, HID, 0);
    gemm_h<<<dim3(SEQ/TBN, (NKV*HD)/TBM), 256, GEMM_SMEM>>>(WVp, HSp, VTp, NKV*HD, SEQ, HID, 1);

    // RMSNorm + RoPE -> fp16; attention scale * log2(e) folded into Q
    norm_rope_h<<<SEQ * NH,  128>>>(Qfp, Q16p, qw, cosv, sinv, NH,
                                    0.08838834764831845f * 1.4426950408889634f);
    norm_rope_h<<<SEQ * NKV, 128>>>(Kfp, K16p, kw, cosv, sinv, NKV, 1.0f);

    // causal flash attention (GQA), fp16 tensor cores
    flash_h<<<dim3(SEQ / FQ, NH), 256, FLASH_SMEM>>>(Q16p, K16p, VTp, AOp);

    // output projection -> fp32 out
    gemm_h<<<dim3(HID/TBN, SEQ/TBM), 256, GEMM_SMEM>>>(AOp, WOp, out, SEQ, HID, HID, 0);
}

// round 7
// speedup vs baseline: 7.1655x; 1.0842x over previous
#include <cuda_runtime.h>
#include <cuda_fp16.h>
#include <math.h>
#include <stdint.h>

#define SEQ   4096
#define HID   2048
#define NH    16
#define NKV   8
#define HD    128

// ---------------- scratch (no allocation allowed) ----------------
__device__ float  g_Qf [SEQ * NH  * HD];
__device__ float  g_Kf [SEQ * NKV * HD];
__device__ __half g_HS16[SEQ * HID];
__device__ __half g_WQ16[NH  * HD * HID];
__device__ __half g_WK16[NKV * HD * HID];
__device__ __half g_WV16[NKV * HD * HID];
__device__ __half g_WO16[HID * NH * HD];
__device__ __half g_Q16 [SEQ * NH  * HD];
__device__ __half g_K16 [SEQ * NKV * HD];
__device__ __half g_VT16[NKV * HD * SEQ];
__device__ __half g_AO16[SEQ * NH  * HD];

// ---------------- PTX helpers ----------------
__device__ __forceinline__ void mma_f16(float& d0, float& d1, float& d2, float& d3,
                                        uint32_t a0, uint32_t a1, uint32_t a2, uint32_t a3,
                                        uint32_t b0, uint32_t b1)
{
    asm volatile(
        "mma.sync.aligned.m16n8k16.row.col.f32.f16.f16.f32 "
        "{%0,%1,%2,%3},{%4,%5,%6,%7},{%8,%9},{%0,%1,%2,%3};\n"
        : "+f"(d0), "+f"(d1), "+f"(d2), "+f"(d3)
        : "r"(a0), "r"(a1), "r"(a2), "r"(a3), "r"(b0), "r"(b1));
}
__device__ __forceinline__ void ldsm_x4(uint32_t& r0, uint32_t& r1,
                                        uint32_t& r2, uint32_t& r3, uint32_t addr)
{
    asm volatile("ldmatrix.sync.aligned.m8n8.x4.shared.b16 {%0,%1,%2,%3}, [%4];"
                 : "=r"(r0), "=r"(r1), "=r"(r2), "=r"(r3) : "r"(addr));
}
__device__ __forceinline__ uint32_t smem_u32(const void* p)
{
    return (uint32_t)__cvta_generic_to_shared(p);
}
__device__ __forceinline__ float ex2f(float x)
{
    float r;
    asm("ex2.approx.ftz.f32 %0, %1;" : "=f"(r) : "f"(x));
    return r;
}
__device__ __forceinline__ uint32_t packh2(float lo, float hi)
{
    __half2 h = __floats2half2_rn(lo, hi);
    return *(uint32_t*)&h;
}
__device__ __forceinline__ void cp_async16(void* smem, const void* gmem)
{
    uint32_t s = smem_u32(smem);
    asm volatile("cp.async.cg.shared.global [%0], [%1], 16;\n" :: "r"(s), "l"(gmem));
}
#define CP_COMMIT()  asm volatile("cp.async.commit_group;\n")
#define CP_WAIT(n)   asm volatile("cp.async.wait_group %0;\n" :: "n"(n))

// =================================================================
// fp32 -> fp16 convert
// =================================================================
__global__ __launch_bounds__(256) void cvt_h(const float4* __restrict__ in,
                                             __half2* __restrict__ out, int n4)
{
    int i = blockIdx.x * blockDim.x + threadIdx.x;
    if (i < n4) {
        float4 v = in[i];
        out[2 * i]     = __floats2half2_rn(v.x, v.y);
        out[2 * i + 1] = __floats2half2_rn(v.z, v.w);
    }
}

// =================================================================
// fp16 NT GEMM (m16n8k16 + ldmatrix): C[M,N] = A[M,K] * B[N,K]^T
// 128x128 tile, BK=64, 256 threads (8 warps 4x2), warp tile 32x64.
// =================================================================
#define TBM 128
#define TBN 128
#define TBK 64
#define TAS 72
#define GSTG (2 * TBM * TAS)
#define GEMM_SMEM (2 * GSTG * 2)

__global__ __launch_bounds__(256) void gemm_h(const __half* __restrict__ A,
                                              const __half* __restrict__ B,
                                              void* __restrict__ Cv,
                                              int M, int N, int K, int out_half)
{
    extern __shared__ __half sh[];

    const int tid  = threadIdx.x;
    const int w    = tid >> 5, lane = tid & 31;
    const int wm   = w >> 1,   wn   = w & 1;
    const int q    = lane >> 2, t = lane & 3;
    const int m0   = blockIdx.y * TBM;
    const int n0   = blockIdx.x * TBN;

    // ldmatrix per-lane offsets (bytes)
    const uint32_t a_loff = (uint32_t)(((wm * 32 + (lane & 15)) * TAS + (lane >> 4) * 8) * 2);
    const uint32_t b_loff = (uint32_t)(((wn * 64 + ((lane >> 4) & 1) * 8 + (lane & 7)) * TAS) * 2
                                       + ((lane >> 3) & 1) * 16);

    float acc[2][8][4];
#pragma unroll
    for (int mt = 0; mt < 2; mt++)
#pragma unroll
        for (int nt = 0; nt < 8; nt++)
#pragma unroll
            for (int c = 0; c < 4; c++) acc[mt][nt][c] = 0.0f;

    const int T = K / TBK;

    auto load_stage = [&](int k0, int st) {
        __half* as = sh + st * GSTG;
        __half* bs = as + TBM * TAS;
#pragma unroll
        for (int it = 0; it < 4; it++) {
            int li  = tid + it * 256;
            int row = li >> 3;
            int c   = (li & 7) * 8;
            cp_async16(as + row * TAS + c, A + (size_t)(m0 + row) * K + k0 + c);
        }
#pragma unroll
        for (int it = 0; it < 4; it++) {
            int li  = tid + it * 256;
            int row = li >> 3;
            int c   = (li & 7) * 8;
            cp_async16(bs + row * TAS + c, B + (size_t)(n0 + row) * K + k0 + c);
        }
        CP_COMMIT();
    };

    load_stage(0, 0);

    for (int ti = 0; ti < T; ti++) {
        const int st = ti & 1;
        if (ti + 1 < T) { load_stage((ti + 1) * TBK, st ^ 1); CP_WAIT(1); }
        else            { CP_WAIT(0); }
        __syncthreads();

        const uint32_t as_u = smem_u32(sh + st * GSTG);
        const uint32_t bs_u = as_u + TBM * TAS * 2;

#pragma unroll
        for (int ks = 0; ks < 4; ks++) {
            const uint32_t kb = ks * 32;     // 16 halves = 32 bytes
            uint32_t af[2][4], bf[8][2];
            ldsm_x4(af[0][0], af[0][1], af[0][2], af[0][3], as_u + a_loff + kb);
            ldsm_x4(af[1][0], af[1][1], af[1][2], af[1][3],
                    as_u + a_loff + 16 * TAS * 2 + kb);
#pragma unroll
            for (int p = 0; p < 4; p++)
                ldsm_x4(bf[2 * p][0], bf[2 * p][1], bf[2 * p + 1][0], bf[2 * p + 1][1],
                        bs_u + b_loff + p * 16 * TAS * 2 + kb);
#pragma unroll
            for (int mt = 0; mt < 2; mt++)
#pragma unroll
                for (int nt = 0; nt < 8; nt++)
                    mma_f16(acc[mt][nt][0], acc[mt][nt][1], acc[mt][nt][2], acc[mt][nt][3],
                            af[mt][0], af[mt][1], af[mt][2], af[mt][3],
                            bf[nt][0], bf[nt][1]);
        }
        __syncthreads();
    }

    if (out_half) {
        __half* C = (__half*)Cv;
#pragma unroll
        for (int mt = 0; mt < 2; mt++) {
            const int row = m0 + wm * 32 + mt * 16 + q;
#pragma unroll
            for (int nt = 0; nt < 8; nt++) {
                const int col = n0 + wn * 64 + nt * 8 + 2 * t;
                *(uint32_t*)(C + (size_t)row * N + col)       = packh2(acc[mt][nt][0], acc[mt][nt][1]);
                *(uint32_t*)(C + (size_t)(row + 8) * N + col) = packh2(acc[mt][nt][2], acc[mt][nt][3]);
            }
        }
    } else {
        float* C = (float*)Cv;
#pragma unroll
        for (int mt = 0; mt < 2; mt++) {
            const int row = m0 + wm * 32 + mt * 16 + q;
#pragma unroll
            for (int nt = 0; nt < 8; nt++) {
                const int col = n0 + wn * 64 + nt * 8 + 2 * t;
                *(float2*)(C + (size_t)row * N + col)       = make_float2(acc[mt][nt][0], acc[mt][nt][1]);
                *(float2*)(C + (size_t)(row + 8) * N + col) = make_float2(acc[mt][nt][2], acc[mt][nt][3]);
            }
        }
    }
}

// =================================================================
// per-head RMSNorm + RoPE: fp32 in -> fp16 out.
// =================================================================
__global__ __launch_bounds__(128) void norm_rope_h(const float* __restrict__ X,
                                                   __half* __restrict__ Y,
                                                   const float* __restrict__ w,
                                                   const float* __restrict__ cosv,
                                                   const float* __restrict__ sinv,
                                                   int heads, float outscale)
{
    const int h = blockIdx.x % heads;
    const int s = blockIdx.x / heads;
    const float* row = X + ((size_t)s * heads + h) * HD;
    __half* out = Y + ((size_t)s * heads + h) * HD;
    const int d = threadIdx.x;

    float x  = row[d];
    float ss = x * x;
#pragma unroll
    for (int off = 16; off > 0; off >>= 1)
        ss += __shfl_xor_sync(0xffffffffu, ss, off);

    __shared__ float sb[4];
    const int warp = d >> 5, lane = d & 31;
    if (lane == 0) sb[warp] = ss;
    __syncthreads();
    float tot = sb[0] + sb[1] + sb[2] + sb[3];
    float xn  = x * rsqrtf(tot * (1.0f / HD) + 1e-6f) * w[d];

    __shared__ float xs[HD];
    xs[d] = xn;
    __syncthreads();
    float other = (d < HD / 2) ? -xs[d + HD / 2] : xs[d - HD / 2];
    float res = (xn * cosv[(size_t)s * HD + d] + other * sinv[(size_t)s * HD + d]) * outscale;
    out[d] = __float2half_rn(res);
}

// =================================================================
// Causal flash attention, fp16 m16n8k16 + ldmatrix.
// =================================================================
#define FQ   128
#define FK   64
#define KSTR 136
#define VTSTR 72
#define QSTR 136
#define KVSTG (FK * KSTR + FQ * VTSTR)
#define FLASH_SMEM (2 * KVSTG * 2)

__global__ __launch_bounds__(256) void flash_h(const __half* __restrict__ Q,
                                               const __half* __restrict__ K,
                                               const __half* __restrict__ VT,
                                               __half* __restrict__ O)
{
    extern __shared__ __half sh[];

    const int tid  = threadIdx.x;
    const int w    = tid >> 5, lane = tid & 31;
    const int q    = lane >> 2, t = lane & 3;
    const int h    = blockIdx.y;
    const int q0   = ((int)gridDim.x - 1 - (int)blockIdx.x) * FQ;
    const int kvh  = h >> 1;
    const int r0   = w * 16;

    const __half* Qb  = Q  + (size_t)h * HD;
    const __half* Kb  = K  + (size_t)kvh * HD;
    const __half* VTb = VT + (size_t)(kvh * HD) * SEQ;

    // B-style ldmatrix lane offsets (bytes)
    const uint32_t k_loff = (uint32_t)(((((lane >> 4) & 1) * 8 + (lane & 7)) * KSTR) * 2
                                       + ((lane >> 3) & 1) * 16);
    const uint32_t v_loff = (uint32_t)(((((lane >> 4) & 1) * 8 + (lane & 7)) * VTSTR) * 2
                                       + ((lane >> 3) & 1) * 16);

    // ---- stage Q in stage0 area, extract fragments via ldmatrix ----
    uint32_t qf[8][4];
    {
        __half* Qs = sh;
#pragma unroll
        for (int it = 0; it < 8; it++) {
            int li = tid + it * 256;
            int r  = li >> 4;
            int c  = (li & 15) * 8;
            *(float4*)(Qs + r * QSTR + c) =
                *(const float4*)(Qb + (size_t)(q0 + r) * (NH * HD) + c);
        }
        __syncthreads();
        const uint32_t qs_u = smem_u32(Qs);
        const uint32_t q_loff = (uint32_t)(((r0 + (lane & 15)) * QSTR + (lane >> 4) * 8) * 2);
#pragma unroll
        for (int ks = 0; ks < 8; ks++)
            ldsm_x4(qf[ks][0], qf[ks][1], qf[ks][2], qf[ks][3], qs_u + q_loff + ks * 32);
        __syncthreads();
    }

    float o[16][4];
    float m_i[2], l_i[2];
#pragma unroll
    for (int hf = 0; hf < 2; hf++) { m_i[hf] = -1e30f; l_i[hf] = 0.0f; }
#pragma unroll
    for (int nt = 0; nt < 16; nt++)
#pragma unroll
        for (int c = 0; c < 4; c++) o[nt][c] = 0.0f;

    const int ktiles = q0 / FK + 2;

    auto prefetch = [&](int kt, int st) {
        __half* Ks = sh + st * KVSTG;
        __half* Vs = Ks + FK * KSTR;
        const int k0 = kt * FK;
#pragma unroll
        for (int it = 0; it < 4; it++) {
            int li = tid + it * 256;
            int r  = li >> 4;
            int c  = (li & 15) * 8;
            cp_async16(Ks + r * KSTR + c, Kb + (size_t)(k0 + r) * (NKV * HD) + c);
        }
#pragma unroll
        for (int it = 0; it < 4; it++) {
            int li = tid + it * 256;
            int r  = li >> 3;
            int c  = (li & 7) * 8;
            cp_async16(Vs + r * VTSTR + c, VTb + (size_t)r * SEQ + k0 + c);
        }
        CP_COMMIT();
    };

    prefetch(0, 0);

    for (int kt = 0; kt < ktiles; kt++) {
        const int st = kt & 1;
        const int k0 = kt * FK;

        if (kt + 1 < ktiles) { prefetch(kt + 1, st ^ 1); CP_WAIT(1); }
        else                 { CP_WAIT(0); }
        __syncthreads();

        const uint32_t ks_u = smem_u32(sh + st * KVSTG);
        const uint32_t vs_u = ks_u + FK * KSTR * 2;

        // ---- S = Q K^T ----
        float s[8][4];
#pragma unroll
        for (int nt = 0; nt < 8; nt++)
#pragma unroll
            for (int c = 0; c < 4; c++) s[nt][c] = 0.0f;

#pragma unroll
        for (int ks = 0; ks < 8; ks++) {
            const uint32_t kb = ks * 32;
            uint32_t bf[8][2];
#pragma unroll
            for (int p = 0; p < 4; p++)
                ldsm_x4(bf[2 * p][0], bf[2 * p][1], bf[2 * p + 1][0], bf[2 * p + 1][1],
                        ks_u + k_loff + p * 16 * KSTR * 2 + kb);
#pragma unroll
            for (int nt = 0; nt < 8; nt++)
                mma_f16(s[nt][0], s[nt][1], s[nt][2], s[nt][3],
                        qf[ks][0], qf[ks][1], qf[ks][2], qf[ks][3],
                        bf[nt][0], bf[nt][1]);
        }

        // ---- causal mask ----
        if (k0 + FK - 1 > q0) {
#pragma unroll
            for (int hf = 0; hf < 2; hf++) {
                const int row = q0 + r0 + q + hf * 8;
#pragma unroll
                for (int nt = 0; nt < 8; nt++) {
                    const int col = k0 + nt * 8 + 2 * t;
                    if (col     > row) s[nt][hf * 2]     = -1e30f;
                    if (col + 1 > row) s[nt][hf * 2 + 1] = -1e30f;
                }
            }
        }

        // ---- online softmax (exp2 domain) ----
#pragma unroll
        for (int hf = 0; hf < 2; hf++) {
            float rm = -1e30f;
#pragma unroll
            for (int nt = 0; nt < 8; nt++)
                rm = fmaxf(rm, fmaxf(s[nt][hf * 2], s[nt][hf * 2 + 1]));
            rm = fmaxf(rm, __shfl_xor_sync(0xffffffffu, rm, 1));
            rm = fmaxf(rm, __shfl_xor_sync(0xffffffffu, rm, 2));

            const float mnew  = fmaxf(m_i[hf], rm);
            const float alpha = ex2f(m_i[hf] - mnew);
            float rs = 0.0f;
#pragma unroll
            for (int nt = 0; nt < 8; nt++) {
                float p0 = ex2f(s[nt][hf * 2]     - mnew);
                float p1 = ex2f(s[nt][hf * 2 + 1] - mnew);
                rs += p0 + p1;
                s[nt][hf * 2]     = p0;
                s[nt][hf * 2 + 1] = p1;
            }
            rs += __shfl_xor_sync(0xffffffffu, rs, 1);
            rs += __shfl_xor_sync(0xffffffffu, rs, 2);

            l_i[hf] = l_i[hf] * alpha + rs;
            m_i[hf] = mnew;

            if (__any_sync(0xffffffffu, alpha != 1.0f)) {
#pragma unroll
                for (int nt = 0; nt < 16; nt++) {
                    o[nt][hf * 2]     *= alpha;
                    o[nt][hf * 2 + 1] *= alpha;
                }
            }
        }

        // ---- pack P -> fp16 A-fragments (register only) ----
        uint32_t paf[4][4];
#pragma unroll
        for (int j = 0; j < 4; j++) {
            paf[j][0] = packh2(s[2 * j][0],     s[2 * j][1]);
            paf[j][1] = packh2(s[2 * j][2],     s[2 * j][3]);
            paf[j][2] = packh2(s[2 * j + 1][0], s[2 * j + 1][1]);
            paf[j][3] = packh2(s[2 * j + 1][2], s[2 * j + 1][3]);
        }

        // ---- O += P V (Vt [d][key]) ----
#pragma unroll
        for (int j = 0; j < 4; j++) {
            const uint32_t kb = j * 32;
            uint32_t bv[16][2];
#pragma unroll
            for (int p = 0; p < 8; p++)
                ldsm_x4(bv[2 * p][0], bv[2 * p][1], bv[2 * p + 1][0], bv[2 * p + 1][1],
                        vs_u + v_loff + p * 16 * VTSTR * 2 + kb);
#pragma unroll
            for (int nt = 0; nt < 16; nt++)
                mma_f16(o[nt][0], o[nt][1], o[nt][2], o[nt][3],
                        paf[j][0], paf[j][1], paf[j][2], paf[j][3],
                        bv[nt][0], bv[nt][1]);
        }
        __syncthreads();
    }

    // ---- epilogue ----
#pragma unroll
    for (int hf = 0; hf < 2; hf++) {
        const float inv = 1.0f / l_i[hf];
        const int row = q0 + r0 + q + hf * 8;
        __half* Orow = O + (size_t)row * (NH * HD) + h * HD;
#pragma unroll
        for (int nt = 0; nt < 16; nt++) {
            const int col = nt * 8 + 2 * t;
            *(uint32_t*)(Orow + col) = packh2(o[nt][hf * 2] * inv, o[nt][hf * 2 + 1] * inv);
        }
    }
}

// =================================================================
// launch
// =================================================================
extern "C" void kernel_launch(void* const* d_in, const int* in_sizes, int n_in,
                              void* d_out, int out_size)
{
    const float* hs   = (const float*)d_in[0];
    const float* cosv = (const float*)d_in[1];
    const float* sinv = (const float*)d_in[2];
    const float* wq   = (const float*)d_in[3];
    const float* wk   = (const float*)d_in[4];
    const float* wv   = (const float*)d_in[5];
    const float* wo   = (const float*)d_in[6];
    const float* qw   = (const float*)d_in[7];
    const float* kw   = (const float*)d_in[8];
    float* out = (float*)d_out;

    float *Qfp, *Kfp;
    __half *HSp, *WQp, *WKp, *WVp, *WOp, *Q16p, *K16p, *VTp, *AOp;
    cudaGetSymbolAddress((void**)&Qfp,  g_Qf);
    cudaGetSymbolAddress((void**)&Kfp,  g_Kf);
    cudaGetSymbolAddress((void**)&HSp,  g_HS16);
    cudaGetSymbolAddress((void**)&WQp,  g_WQ16);
    cudaGetSymbolAddress((void**)&WKp,  g_WK16);
    cudaGetSymbolAddress((void**)&WVp,  g_WV16);
    cudaGetSymbolAddress((void**)&WOp,  g_WO16);
    cudaGetSymbolAddress((void**)&Q16p, g_Q16);
    cudaGetSymbolAddress((void**)&K16p, g_K16);
    cudaGetSymbolAddress((void**)&VTp,  g_VT16);
    cudaGetSymbolAddress((void**)&AOp,  g_AO16);

    cudaFuncSetAttribute(gemm_h,  cudaFuncAttributeMaxDynamicSharedMemorySize, GEMM_SMEM);
    cudaFuncSetAttribute(flash_h, cudaFuncAttributeMaxDynamicSharedMemorySize, FLASH_SMEM);

    const int RB = 256;
    cvt_h<<<(SEQ*HID/4 + RB-1)/RB, RB>>>((const float4*)hs, (__half2*)HSp, SEQ*HID/4);
    cvt_h<<<(NH*HD*HID/4 + RB-1)/RB, RB>>>((const float4*)wq, (__half2*)WQp, NH*HD*HID/4);
    cvt_h<<<(NKV*HD*HID/4 + RB-1)/RB, RB>>>((const float4*)wk, (__half2*)WKp, NKV*HD*HID/4);
    cvt_h<<<(NKV*HD*HID/4 + RB-1)/RB, RB>>>((const float4*)wv, (__half2*)WVp, NKV*HD*HID/4);
    cvt_h<<<(HID*NH*HD/4 + RB-1)/RB, RB>>>((const float4*)wo, (__half2*)WOp, HID*NH*HD/4);

    gemm_h<<<dim3((NH*HD)/TBN,  SEQ/TBM), 256, GEMM_SMEM>>>(HSp, WQp, Qfp, SEQ, NH*HD,  HID, 0);
    gemm_h<<<dim3((NKV*HD)/TBN, SEQ/TBM), 256, GEMM_SMEM>>>(HSp, WKp, Kfp, SEQ, NKV*HD, HID, 0);
    gemm_h<<<dim3(SEQ/TBN, (NKV*HD)/TBM), 256, GEMM_SMEM>>>(WVp, HSp, VTp, NKV*HD, SEQ, HID, 1);

    norm_rope_h<<<SEQ * NH,  128>>>(Qfp, Q16p, qw, cosv, sinv, NH,
                                    0.08838834764831845f * 1.4426950408889634f);
    norm_rope_h<<<SEQ * NKV, 128>>>(Kfp, K16p, kw, cosv, sinv, NKV, 1.0f);

    flash_h<<<dim3(SEQ / FQ, NH), 256, FLASH_SMEM>>>(Q16p, K16p, VTp, AOp);

    gemm_h<<<dim3(HID/TBN, SEQ/TBM), 256, GEMM_SMEM>>>(AOp, WOp, out, SEQ, HID, HID, 0);
}

// round 8
// speedup vs baseline: 7.3592x; 1.0270x over previous
#include <cuda_runtime.h>
#include <cuda_fp16.h>
#include <math.h>
#include <stdint.h>

#define SEQ   4096
#define HID   2048
#define NH    16
#define NKV   8
#define HD    128

// ---------------- scratch (no allocation allowed) ----------------
__device__ __half g_HS16[SEQ * HID];
__device__ __half g_WQ16[NH  * HD * HID];
__device__ __half g_WK16[NKV * HD * HID];
__device__ __half g_WV16[NKV * HD * HID];
__device__ __half g_WO16[HID * NH * HD];
__device__ __half g_Q16 [SEQ * NH  * HD];
__device__ __half g_K16 [SEQ * NKV * HD];
__device__ __half g_VT16[NKV * HD * SEQ];
__device__ __half g_AO16[SEQ * NH  * HD];

// ---------------- PTX helpers ----------------
__device__ __forceinline__ void mma_f16(float& d0, float& d1, float& d2, float& d3,
                                        uint32_t a0, uint32_t a1, uint32_t a2, uint32_t a3,
                                        uint32_t b0, uint32_t b1)
{
    asm volatile(
        "mma.sync.aligned.m16n8k16.row.col.f32.f16.f16.f32 "
        "{%0,%1,%2,%3},{%4,%5,%6,%7},{%8,%9},{%0,%1,%2,%3};\n"
        : "+f"(d0), "+f"(d1), "+f"(d2), "+f"(d3)
        : "r"(a0), "r"(a1), "r"(a2), "r"(a3), "r"(b0), "r"(b1));
}
__device__ __forceinline__ void ldsm_x4(uint32_t& r0, uint32_t& r1,
                                        uint32_t& r2, uint32_t& r3, uint32_t addr)
{
    asm volatile("ldmatrix.sync.aligned.m8n8.x4.shared.b16 {%0,%1,%2,%3}, [%4];"
                 : "=r"(r0), "=r"(r1), "=r"(r2), "=r"(r3) : "r"(addr));
}
__device__ __forceinline__ uint32_t smem_u32(const void* p)
{
    return (uint32_t)__cvta_generic_to_shared(p);
}
__device__ __forceinline__ float ex2f(float x)
{
    float r;
    asm("ex2.approx.ftz.f32 %0, %1;" : "=f"(r) : "f"(x));
    return r;
}
__device__ __forceinline__ uint32_t packh2(float lo, float hi)
{
    __half2 h = __floats2half2_rn(lo, hi);
    return *(uint32_t*)&h;
}
__device__ __forceinline__ void cp_async16(void* smem, const void* gmem)
{
    uint32_t s = smem_u32(smem);
    asm volatile("cp.async.cg.shared.global [%0], [%1], 16;\n" :: "r"(s), "l"(gmem));
}
#define CP_COMMIT()  asm volatile("cp.async.commit_group;\n")
#define CP_WAIT(n)   asm volatile("cp.async.wait_group %0;\n" :: "n"(n))

// =================================================================
// batched fp32 -> fp16 convert: 5 arrays in one launch (grid.y = job)
// =================================================================
__global__ __launch_bounds__(256) void cvt_h5(
    const float4* s0, __half2* d0, int n0,
    const float4* s1, __half2* d1, int n1,
    const float4* s2, __half2* d2, int n2,
    const float4* s3, __half2* d3, int n3,
    const float4* s4, __half2* d4, int n4)
{
    const float4* src; __half2* dst; int n;
    switch (blockIdx.y) {
        case 0: src = s0; dst = d0; n = n0; break;
        case 1: src = s1; dst = d1; n = n1; break;
        case 2: src = s2; dst = d2; n = n2; break;
        case 3: src = s3; dst = d3; n = n3; break;
        default: src = s4; dst = d4; n = n4; break;
    }
    int i = blockIdx.x * blockDim.x + threadIdx.x;
    if (i < n) {
        float4 v = src[i];
        dst[2 * i]     = __floats2half2_rn(v.x, v.y);
        dst[2 * i + 1] = __floats2half2_rn(v.z, v.w);
    }
}

// =================================================================
// fp16 NT GEMM (m16n8k16 + ldmatrix): C[M,N] = A[M,K] * B[N,K]^T
// 128x128 tile, BK=64, 256 threads (8 warps 4x2), warp tile 32x64.
// mode 0: fp32 C.  mode 1: fp16 C.
// mode 2: fused per-head RMSNorm + RoPE -> fp16 C  (requires TBN == HD,
//         so each CTA owns complete head-rows; partner col = col^64).
// =================================================================
#define TBM 128
#define TBN 128
#define TBK 64
#define TAS 72
#define GSTG (2 * TBM * TAS)
#define GEMM_SMEM (2 * GSTG * 2)
#define XS 132        // fp32 stride of epilogue exchange buffer

__global__ __launch_bounds__(256) void gemm_h(const __half* __restrict__ A,
                                              const __half* __restrict__ B,
                                              void* __restrict__ Cv,
                                              int M, int N, int K, int mode,
                                              const float* __restrict__ nw,
                                              const float* __restrict__ cosv,
                                              const float* __restrict__ sinv,
                                              float outscale)
{
    extern __shared__ __half sh[];

    const int tid  = threadIdx.x;
    const int w    = tid >> 5, lane = tid & 31;
    const int wm   = w >> 1,   wn   = w & 1;
    const int q    = lane >> 2, t = lane & 3;
    const int m0   = blockIdx.y * TBM;
    const int n0   = blockIdx.x * TBN;

    const uint32_t a_loff = (uint32_t)(((wm * 32 + (lane & 15)) * TAS + (lane >> 4) * 8) * 2);
    const uint32_t b_loff = (uint32_t)(((wn * 64 + ((lane >> 4) & 1) * 8 + (lane & 7)) * TAS) * 2
                                       + ((lane >> 3) & 1) * 16);

    float acc[2][8][4];
#pragma unroll
    for (int mt = 0; mt < 2; mt++)
#pragma unroll
        for (int nt = 0; nt < 8; nt++)
#pragma unroll
            for (int c = 0; c < 4; c++) acc[mt][nt][c] = 0.0f;

    const int T = K / TBK;

    auto load_stage = [&](int k0, int st) {
        __half* as = sh + st * GSTG;
        __half* bs = as + TBM * TAS;
#pragma unroll
        for (int it = 0; it < 4; it++) {
            int li  = tid + it * 256;
            int row = li >> 3;
            int c   = (li & 7) * 8;
            cp_async16(as + row * TAS + c, A + (size_t)(m0 + row) * K + k0 + c);
        }
#pragma unroll
        for (int it = 0; it < 4; it++) {
            int li  = tid + it * 256;
            int row = li >> 3;
            int c   = (li & 7) * 8;
            cp_async16(bs + row * TAS + c, B + (size_t)(n0 + row) * K + k0 + c);
        }
        CP_COMMIT();
    };

    load_stage(0, 0);

    for (int ti = 0; ti < T; ti++) {
        const int st = ti & 1;
        if (ti + 1 < T) { load_stage((ti + 1) * TBK, st ^ 1); CP_WAIT(1); }
        else            { CP_WAIT(0); }
        __syncthreads();

        const uint32_t as_u = smem_u32(sh + st * GSTG);
        const uint32_t bs_u = as_u + TBM * TAS * 2;

#pragma unroll
        for (int ks = 0; ks < 4; ks++) {
            const uint32_t kb = ks * 32;
            uint32_t af[2][4], bf[8][2];
            ldsm_x4(af[0][0], af[0][1], af[0][2], af[0][3], as_u + a_loff + kb);
            ldsm_x4(af[1][0], af[1][1], af[1][2], af[1][3],
                    as_u + a_loff + 16 * TAS * 2 + kb);
#pragma unroll
            for (int p = 0; p < 4; p++)
                ldsm_x4(bf[2 * p][0], bf[2 * p][1], bf[2 * p + 1][0], bf[2 * p + 1][1],
                        bs_u + b_loff + p * 16 * TAS * 2 + kb);
#pragma unroll
            for (int mt = 0; mt < 2; mt++)
#pragma unroll
                for (int nt = 0; nt < 8; nt++)
                    mma_f16(acc[mt][nt][0], acc[mt][nt][1], acc[mt][nt][2], acc[mt][nt][3],
                            af[mt][0], af[mt][1], af[mt][2], af[mt][3],
                            bf[nt][0], bf[nt][1]);
        }
        __syncthreads();
    }

    if (mode == 0) {
        float* C = (float*)Cv;
#pragma unroll
        for (int mt = 0; mt < 2; mt++) {
            const int row = m0 + wm * 32 + mt * 16 + q;
#pragma unroll
            for (int nt = 0; nt < 8; nt++) {
                const int col = n0 + wn * 64 + nt * 8 + 2 * t;
                *(float2*)(C + (size_t)row * N + col)       = make_float2(acc[mt][nt][0], acc[mt][nt][1]);
                *(float2*)(C + (size_t)(row + 8) * N + col) = make_float2(acc[mt][nt][2], acc[mt][nt][3]);
            }
        }
    } else if (mode == 1) {
        __half* C = (__half*)Cv;
#pragma unroll
        for (int mt = 0; mt < 2; mt++) {
            const int row = m0 + wm * 32 + mt * 16 + q;
#pragma unroll
            for (int nt = 0; nt < 8; nt++) {
                const int col = n0 + wn * 64 + nt * 8 + 2 * t;
                *(uint32_t*)(C + (size_t)row * N + col)       = packh2(acc[mt][nt][0], acc[mt][nt][1]);
                *(uint32_t*)(C + (size_t)(row + 8) * N + col) = packh2(acc[mt][nt][2], acc[mt][nt][3]);
            }
        }
    } else {
        // ---- fused RMSNorm + RoPE epilogue (one head per CTA column) ----
        float* red  = (float*)sh;          // [128][2] partial sums
        float* xbuf = (float*)sh + 256;    // [128][132] normalized*w values

        // 1) per-row sum of squares (this warp-half's 64 cols)
#pragma unroll
        for (int mt = 0; mt < 2; mt++)
#pragma unroll
            for (int hf = 0; hf < 2; hf++) {
                float ss = 0.0f;
#pragma unroll
                for (int nt = 0; nt < 8; nt++) {
                    float a0 = acc[mt][nt][hf * 2], a1 = acc[mt][nt][hf * 2 + 1];
                    ss += a0 * a0 + a1 * a1;
                }
                ss += __shfl_xor_sync(0xffffffffu, ss, 1);
                ss += __shfl_xor_sync(0xffffffffu, ss, 2);
                if (t == 0) red[(wm * 32 + mt * 16 + q + hf * 8) * 2 + wn] = ss;
            }
        __syncthreads();

        // 2) normalize, apply norm weight, stage to xbuf
#pragma unroll
        for (int mt = 0; mt < 2; mt++)
#pragma unroll
            for (int hf = 0; hf < 2; hf++) {
                const int row = wm * 32 + mt * 16 + q + hf * 8;
                const float tot = red[row * 2] + red[row * 2 + 1];
                const float rms = rsqrtf(tot * (1.0f / HD) + 1e-6f);
#pragma unroll
                for (int nt = 0; nt < 8; nt++) {
                    const int col = wn * 64 + nt * 8 + 2 * t;
                    xbuf[row * XS + col]     = acc[mt][nt][hf * 2]     * rms * nw[col];
                    xbuf[row * XS + col + 1] = acc[mt][nt][hf * 2 + 1] * rms * nw[col + 1];
                }
            }
        __syncthreads();

        // 3) RoPE (partner = col^64, sign by half) + fp16 store
        __half* C = (__half*)Cv;
        const float sgn = (wn == 0) ? -1.0f : 1.0f;
#pragma unroll
        for (int mt = 0; mt < 2; mt++)
#pragma unroll
            for (int hf = 0; hf < 2; hf++) {
                const int row = wm * 32 + mt * 16 + q + hf * 8;
                const int s   = m0 + row;
                __half* Orow  = C + (size_t)s * N + n0;
#pragma unroll
                for (int nt = 0; nt < 8; nt++) {
                    const int col = wn * 64 + nt * 8 + 2 * t;
                    float x0 = xbuf[row * XS + col];
                    float x1 = xbuf[row * XS + col + 1];
                    float p0 = xbuf[row * XS + (col ^ 64)];
                    float p1 = xbuf[row * XS + (col ^ 64) + 1];
                    float2 cs = *(const float2*)(cosv + (size_t)s * HD + col);
                    float2 sn = *(const float2*)(sinv + (size_t)s * HD + col);
                    float r0 = (x0 * cs.x + sgn * p0 * sn.x) * outscale;
                    float r1 = (x1 * cs.y + sgn * p1 * sn.y) * outscale;
                    *(uint32_t*)(Orow + col) = packh2(r0, r1);
                }
            }
    }
}

// =================================================================
// Causal flash attention, fp16 m16n8k16 + ldmatrix (unchanged R7 core).
// =================================================================
#define FQ   128
#define FK   64
#define KSTR 136
#define VTSTR 72
#define QSTR 136
#define KVSTG (FK * KSTR + FQ * VTSTR)
#define FLASH_SMEM (2 * KVSTG * 2)

__global__ __launch_bounds__(256) void flash_h(const __half* __restrict__ Q,
                                               const __half* __restrict__ K,
                                               const __half* __restrict__ VT,
                                               __half* __restrict__ O)
{
    extern __shared__ __half sh[];

    const int tid  = threadIdx.x;
    const int w    = tid >> 5, lane = tid & 31;
    const int q    = lane >> 2, t = lane & 3;
    const int h    = blockIdx.y;
    const int q0   = ((int)gridDim.x - 1 - (int)blockIdx.x) * FQ;
    const int kvh  = h >> 1;
    const int r0   = w * 16;

    const __half* Qb  = Q  + (size_t)h * HD;
    const __half* Kb  = K  + (size_t)kvh * HD;
    const __half* VTb = VT + (size_t)(kvh * HD) * SEQ;

    const uint32_t k_loff = (uint32_t)(((((lane >> 4) & 1) * 8 + (lane & 7)) * KSTR) * 2
                                       + ((lane >> 3) & 1) * 16);
    const uint32_t v_loff = (uint32_t)(((((lane >> 4) & 1) * 8 + (lane & 7)) * VTSTR) * 2
                                       + ((lane >> 3) & 1) * 16);

    uint32_t qf[8][4];
    {
        __half* Qs = sh;
#pragma unroll
        for (int it = 0; it < 8; it++) {
            int li = tid + it * 256;
            int r  = li >> 4;
            int c  = (li & 15) * 8;
            *(float4*)(Qs + r * QSTR + c) =
                *(const float4*)(Qb + (size_t)(q0 + r) * (NH * HD) + c);
        }
        __syncthreads();
        const uint32_t qs_u = smem_u32(Qs);
        const uint32_t q_loff = (uint32_t)(((r0 + (lane & 15)) * QSTR + (lane >> 4) * 8) * 2);
#pragma unroll
        for (int ks = 0; ks < 8; ks++)
            ldsm_x4(qf[ks][0], qf[ks][1], qf[ks][2], qf[ks][3], qs_u + q_loff + ks * 32);
        __syncthreads();
    }

    float o[16][4];
    float m_i[2], l_i[2];
#pragma unroll
    for (int hf = 0; hf < 2; hf++) { m_i[hf] = -1e30f; l_i[hf] = 0.0f; }
#pragma unroll
    for (int nt = 0; nt < 16; nt++)
#pragma unroll
        for (int c = 0; c < 4; c++) o[nt][c] = 0.0f;

    const int ktiles = q0 / FK + 2;

    auto prefetch = [&](int kt, int st) {
        __half* Ks = sh + st * KVSTG;
        __half* Vs = Ks + FK * KSTR;
        const int k0 = kt * FK;
#pragma unroll
        for (int it = 0; it < 4; it++) {
            int li = tid + it * 256;
            int r  = li >> 4;
            int c  = (li & 15) * 8;
            cp_async16(Ks + r * KSTR + c, Kb + (size_t)(k0 + r) * (NKV * HD) + c);
        }
#pragma unroll
        for (int it = 0; it < 4; it++) {
            int li = tid + it * 256;
            int r  = li >> 3;
            int c  = (li & 7) * 8;
            cp_async16(Vs + r * VTSTR + c, VTb + (size_t)r * SEQ + k0 + c);
        }
        CP_COMMIT();
    };

    prefetch(0, 0);

    for (int kt = 0; kt < ktiles; kt++) {
        const int st = kt & 1;
        const int k0 = kt * FK;

        if (kt + 1 < ktiles) { prefetch(kt + 1, st ^ 1); CP_WAIT(1); }
        else                 { CP_WAIT(0); }
        __syncthreads();

        const uint32_t ks_u = smem_u32(sh + st * KVSTG);
        const uint32_t vs_u = ks_u + FK * KSTR * 2;

        float s[8][4];
#pragma unroll
        for (int nt = 0; nt < 8; nt++)
#pragma unroll
            for (int c = 0; c < 4; c++) s[nt][c] = 0.0f;

#pragma unroll
        for (int ks = 0; ks < 8; ks++) {
            const uint32_t kb = ks * 32;
            uint32_t bf[8][2];
#pragma unroll
            for (int p = 0; p < 4; p++)
                ldsm_x4(bf[2 * p][0], bf[2 * p][1], bf[2 * p + 1][0], bf[2 * p + 1][1],
                        ks_u + k_loff + p * 16 * KSTR * 2 + kb);
#pragma unroll
            for (int nt = 0; nt < 8; nt++)
                mma_f16(s[nt][0], s[nt][1], s[nt][2], s[nt][3],
                        qf[ks][0], qf[ks][1], qf[ks][2], qf[ks][3],
                        bf[nt][0], bf[nt][1]);
        }

        if (k0 + FK - 1 > q0) {
#pragma unroll
            for (int hf = 0; hf < 2; hf++) {
                const int row = q0 + r0 + q + hf * 8;
#pragma unroll
                for (int nt = 0; nt < 8; nt++) {
                    const int col = k0 + nt * 8 + 2 * t;
                    if (col     > row) s[nt][hf * 2]     = -1e30f;
                    if (col + 1 > row) s[nt][hf * 2 + 1] = -1e30f;
                }
            }
        }

#pragma unroll
        for (int hf = 0; hf < 2; hf++) {
            float rm = -1e30f;
#pragma unroll
            for (int nt = 0; nt < 8; nt++)
                rm = fmaxf(rm, fmaxf(s[nt][hf * 2], s[nt][hf * 2 + 1]));
            rm = fmaxf(rm, __shfl_xor_sync(0xffffffffu, rm, 1));
            rm = fmaxf(rm, __shfl_xor_sync(0xffffffffu, rm, 2));

            const float mnew  = fmaxf(m_i[hf], rm);
            const float alpha = ex2f(m_i[hf] - mnew);
            float rs = 0.0f;
#pragma unroll
            for (int nt = 0; nt < 8; nt++) {
                float p0 = ex2f(s[nt][hf * 2]     - mnew);
                float p1 = ex2f(s[nt][hf * 2 + 1] - mnew);
                rs += p0 + p1;
                s[nt][hf * 2]     = p0;
                s[nt][hf * 2 + 1] = p1;
            }
            rs += __shfl_xor_sync(0xffffffffu, rs, 1);
            rs += __shfl_xor_sync(0xffffffffu, rs, 2);

            l_i[hf] = l_i[hf] * alpha + rs;
            m_i[hf] = mnew;

            if (__any_sync(0xffffffffu, alpha != 1.0f)) {
#pragma unroll
                for (int nt = 0; nt < 16; nt++) {
                    o[nt][hf * 2]     *= alpha;
                    o[nt][hf * 2 + 1] *= alpha;
                }
            }
        }

        uint32_t paf[4][4];
#pragma unroll
        for (int j = 0; j < 4; j++) {
            paf[j][0] = packh2(s[2 * j][0],     s[2 * j][1]);
            paf[j][1] = packh2(s[2 * j][2],     s[2 * j][3]);
            paf[j][2] = packh2(s[2 * j + 1][0], s[2 * j + 1][1]);
            paf[j][3] = packh2(s[2 * j + 1][2], s[2 * j + 1][3]);
        }

#pragma unroll
        for (int j = 0; j < 4; j++) {
            const uint32_t kb = j * 32;
            uint32_t bv[16][2];
#pragma unroll
            for (int p = 0; p < 8; p++)
                ldsm_x4(bv[2 * p][0], bv[2 * p][1], bv[2 * p + 1][0], bv[2 * p + 1][1],
                        vs_u + v_loff + p * 16 * VTSTR * 2 + kb);
#pragma unroll
            for (int nt = 0; nt < 16; nt++)
                mma_f16(o[nt][0], o[nt][1], o[nt][2], o[nt][3],
                        paf[j][0], paf[j][1], paf[j][2], paf[j][3],
                        bv[nt][0], bv[nt][1]);
        }
        __syncthreads();
    }

#pragma unroll
    for (int hf = 0; hf < 2; hf++) {
        const float inv = 1.0f / l_i[hf];
        const int row = q0 + r0 + q + hf * 8;
        __half* Orow = O + (size_t)row * (NH * HD) + h * HD;
#pragma unroll
        for (int nt = 0; nt < 16; nt++) {
            const int col = nt * 8 + 2 * t;
            *(uint32_t*)(Orow + col) = packh2(o[nt][hf * 2] * inv, o[nt][hf * 2 + 1] * inv);
        }
    }
}

// =================================================================
// launch
// =================================================================
extern "C" void kernel_launch(void* const* d_in, const int* in_sizes, int n_in,
                              void* d_out, int out_size)
{
    const float* hs   = (const float*)d_in[0];
    const float* cosv = (const float*)d_in[1];
    const float* sinv = (const float*)d_in[2];
    const float* wq   = (const float*)d_in[3];
    const float* wk   = (const float*)d_in[4];
    const float* wv   = (const float*)d_in[5];
    const float* wo   = (const float*)d_in[6];
    const float* qw   = (const float*)d_in[7];
    const float* kw   = (const float*)d_in[8];
    float* out = (float*)d_out;

    __half *HSp, *WQp, *WKp, *WVp, *WOp, *Q16p, *K16p, *VTp, *AOp;
    cudaGetSymbolAddress((void**)&HSp,  g_HS16);
    cudaGetSymbolAddress((void**)&WQp,  g_WQ16);
    cudaGetSymbolAddress((void**)&WKp,  g_WK16);
    cudaGetSymbolAddress((void**)&WVp,  g_WV16);
    cudaGetSymbolAddress((void**)&WOp,  g_WO16);
    cudaGetSymbolAddress((void**)&Q16p, g_Q16);
    cudaGetSymbolAddress((void**)&K16p, g_K16);
    cudaGetSymbolAddress((void**)&VTp,  g_VT16);
    cudaGetSymbolAddress((void**)&AOp,  g_AO16);

    cudaFuncSetAttribute(gemm_h,  cudaFuncAttributeMaxDynamicSharedMemorySize, GEMM_SMEM);
    cudaFuncSetAttribute(flash_h, cudaFuncAttributeMaxDynamicSharedMemorySize, FLASH_SMEM);

    // single batched fp32->fp16 conversion launch
    const int n4_hs = SEQ * HID / 4;
    const int n4_wq = NH * HD * HID / 4;
    const int n4_wk = NKV * HD * HID / 4;
    const int n4_wv = NKV * HD * HID / 4;
    const int n4_wo = HID * NH * HD / 4;
    {
        int maxn4 = n4_hs;
        dim3 grid((maxn4 + 255) / 256, 5);
        cvt_h5<<<grid, 256>>>((const float4*)hs, (__half2*)HSp, n4_hs,
                              (const float4*)wq, (__half2*)WQp, n4_wq,
                              (const float4*)wk, (__half2*)WKp, n4_wk,
                              (const float4*)wv, (__half2*)WVp, n4_wv,
                              (const float4*)wo, (__half2*)WOp, n4_wo);
    }

    const float QSCALE = 0.08838834764831845f * 1.4426950408889634f;

    // Q/K projections with fused RMSNorm+RoPE -> fp16
    gemm_h<<<dim3((NH*HD)/TBN,  SEQ/TBM), 256, GEMM_SMEM>>>(HSp, WQp, Q16p, SEQ, NH*HD,  HID, 2,
                                                            qw, cosv, sinv, QSCALE);
    gemm_h<<<dim3((NKV*HD)/TBN, SEQ/TBM), 256, GEMM_SMEM>>>(HSp, WKp, K16p, SEQ, NKV*HD, HID, 2,
                                                            kw, cosv, sinv, 1.0f);
    // V^T = WV * HS^T -> fp16
    gemm_h<<<dim3(SEQ/TBN, (NKV*HD)/TBM), 256, GEMM_SMEM>>>(WVp, HSp, VTp, NKV*HD, SEQ, HID, 1,
                                                            nullptr, nullptr, nullptr, 0.0f);

    // causal flash attention (GQA)
    flash_h<<<dim3(SEQ / FQ, NH), 256, FLASH_SMEM>>>(Q16p, K16p, VTp, AOp);

    // output projection -> fp32 out
    gemm_h<<<dim3(HID/TBN, SEQ/TBM), 256, GEMM_SMEM>>>(AOp, WOp, out, SEQ, HID, HID, 0,
                                                       nullptr, nullptr, nullptr, 0.0f);
}